// round 1
// baseline (speedup 1.0000x reference)
#include <cuda_runtime.h>
#include <math.h>

#define BB 8
#define LL 2048
#define HH 256
#define MTOT (BB*LL)

// Scratch for projected Q/K/V (48 MB total) — static __device__ arrays per the
// no-allocation rules.
__device__ float g_Q[MTOT*HH];
__device__ float g_K[MTOT*HH];
__device__ float g_V[MTOT*HH];

// ---------------------------------------------------------------------------
// QKV projection: Y[m][n] = sum_k X[m][k] * W[n][k]   (y = x @ W^T)
// M=16384, N=256, K=256. 64x64 block tile, 256 threads, 4x4 microtile.
// blockIdx.z selects (Wq->g_Q, Wk->g_K, Wv->g_V).
// ---------------------------------------------------------------------------
__global__ __launch_bounds__(256) void qkv_kernel(
    const float* __restrict__ X,
    const float* __restrict__ Wq,
    const float* __restrict__ Wk,
    const float* __restrict__ Wv)
{
    __shared__ float sA[16][64];
    __shared__ float sB[16][64];

    const float* W;
    float* Y;
    if (blockIdx.z == 0)      { W = Wq; Y = g_Q; }
    else if (blockIdx.z == 1) { W = Wk; Y = g_K; }
    else                      { W = Wv; Y = g_V; }

    const int m0  = blockIdx.y * 64;
    const int n0  = blockIdx.x * 64;
    const int tid = threadIdx.x;
    const int row = tid >> 2;      // 0..63
    const int kq  = tid & 3;       // float4 slot within 16-wide k-chunk
    const int ty  = tid >> 4;      // 0..15
    const int tx  = tid & 15;      // 0..15

    float c[4][4] = {};

    for (int kc = 0; kc < HH; kc += 16) {
        // prefetch
        float4 a  = *(const float4*)&X[(m0 + row) * HH + kc + kq * 4];
        float4 bv = *(const float4*)&W[(n0 + row) * HH + kc + kq * 4];
        __syncthreads();
        sA[kq*4+0][row] = a.x;  sA[kq*4+1][row] = a.y;
        sA[kq*4+2][row] = a.z;  sA[kq*4+3][row] = a.w;
        sB[kq*4+0][row] = bv.x; sB[kq*4+1][row] = bv.y;
        sB[kq*4+2][row] = bv.z; sB[kq*4+3][row] = bv.w;
        __syncthreads();

        #pragma unroll
        for (int kk = 0; kk < 16; kk++) {
            float4 av = *(const float4*)&sA[kk][ty * 4];
            float4 bw = *(const float4*)&sB[kk][tx * 4];
            c[0][0] += av.x * bw.x; c[0][1] += av.x * bw.y; c[0][2] += av.x * bw.z; c[0][3] += av.x * bw.w;
            c[1][0] += av.y * bw.x; c[1][1] += av.y * bw.y; c[1][2] += av.y * bw.z; c[1][3] += av.y * bw.w;
            c[2][0] += av.z * bw.x; c[2][1] += av.z * bw.y; c[2][2] += av.z * bw.z; c[2][3] += av.z * bw.w;
            c[3][0] += av.w * bw.x; c[3][1] += av.w * bw.y; c[3][2] += av.w * bw.z; c[3][3] += av.w * bw.w;
        }
    }

    #pragma unroll
    for (int i = 0; i < 4; i++) {
        float4 o = make_float4(c[i][0], c[i][1], c[i][2], c[i][3]);
        *(float4*)&Y[(m0 + ty*4 + i) * HH + n0 + tx*4] = o;
    }
}

// ---------------------------------------------------------------------------
// Flash attention: one block per (64-query tile, batch).
// Streams 64-key tiles; d=256 processed in two 128-wide chunks through a
// shared 32KB K/V staging buffer. fp32 everywhere.
//
// Shared layout (dynamic, 114688 B):
//   sQ  [256][64]  Q transposed (k-major)        16384 floats
//   sKV [128][64] as K^T chunk / [64][128] as V    8192 floats
//   sP  [64][64]  probabilities                    4096 floats
//
// Thread mapping (256 threads, ty=tid>>4, tx=tid&15):
//   S phase : rows 4*ty..+3, cols 4*tx..+3  (4x4 microtile)
//   PV/O    : rows 4*ty..+3, d-cols {ch*128 + half*64 + 4*tx ..+3}
// Row ownership identical in both phases -> softmax m/l kept in registers,
// replicated across the 16-lane half-warp via __shfl_xor reductions.
// ---------------------------------------------------------------------------
__global__ __launch_bounds__(256, 2) void attn_kernel(
    const int* __restrict__ lens,
    float* __restrict__ out)
{
    extern __shared__ float sm[];
    float* sQ  = sm;            // 16384 floats
    float* sKV = sm + 16384;    //  8192 floats
    float* sP  = sm + 24576;    //  4096 floats

    const int b   = blockIdx.y;
    const int q0  = blockIdx.x * 64;
    const int tid = threadIdx.x;
    const int ty  = tid >> 4;
    const int tx  = tid & 15;
    const int len = lens[b];

    const float* gQb = g_Q + (b * LL + q0) * HH;
    const float* gKb = g_K + b * LL * HH;
    const float* gVb = g_V + b * LL * HH;

    // ---- load Q tile transposed into sQ[k][q] ----
    #pragma unroll
    for (int it = 0; it < 16; it++) {
        int v   = tid + it * 256;   // float4 index 0..4095
        int row = v >> 6;           // 0..63 (query)
        int k4  = v & 63;           // float4 along d
        float4 a = *(const float4*)&gQb[row * HH + k4 * 4];
        sQ[(k4*4+0)*64 + row] = a.x;
        sQ[(k4*4+1)*64 + row] = a.y;
        sQ[(k4*4+2)*64 + row] = a.z;
        sQ[(k4*4+3)*64 + row] = a.w;
    }

    float acc[4][16];
    #pragma unroll
    for (int i = 0; i < 4; i++)
        #pragma unroll
        for (int j = 0; j < 16; j++) acc[i][j] = 0.f;

    float mrow[4], lrow[4];
    #pragma unroll
    for (int i = 0; i < 4; i++) { mrow[i] = -1e30f; lrow[i] = 0.f; }

    const int nkt = (len + 63) >> 6;

    for (int kt = 0; kt < nkt; kt++) {
        const int k0 = kt * 64;
        float s[4][4] = {};

        // ---- S = Q K^T over two 128-wide d-chunks ----
        #pragma unroll
        for (int ch = 0; ch < 2; ch++) {
            // load K chunk transposed: thread owns key row c = tid>>2,
            // d-segment (tid&3)*32 .. +31 (coalesced LDG, 4-way STS)
            {
                const int c     = tid >> 2;
                const int dbase = (tid & 3) * 32;
                const float* src = &gKb[(k0 + c) * HH + ch * 128 + dbase];
                float4 kr[8];
                #pragma unroll
                for (int it = 0; it < 8; it++) kr[it] = *(const float4*)&src[it * 4];
                __syncthreads();   // previous sKV readers done (also guards sQ on kt=0)
                #pragma unroll
                for (int it = 0; it < 8; it++) {
                    int d = dbase + it * 4;
                    sKV[(d+0)*64 + c] = kr[it].x;
                    sKV[(d+1)*64 + c] = kr[it].y;
                    sKV[(d+2)*64 + c] = kr[it].z;
                    sKV[(d+3)*64 + c] = kr[it].w;
                }
            }
            __syncthreads();

            #pragma unroll 16
            for (int kk = 0; kk < 128; kk++) {
                float4 qv = *(const float4*)&sQ[(ch*128 + kk)*64 + ty*4];
                float4 kv = *(const float4*)&sKV[kk*64 + tx*4];
                s[0][0] += qv.x*kv.x; s[0][1] += qv.x*kv.y; s[0][2] += qv.x*kv.z; s[0][3] += qv.x*kv.w;
                s[1][0] += qv.y*kv.x; s[1][1] += qv.y*kv.y; s[1][2] += qv.y*kv.z; s[1][3] += qv.y*kv.w;
                s[2][0] += qv.z*kv.x; s[2][1] += qv.z*kv.y; s[2][2] += qv.z*kv.z; s[2][3] += qv.z*kv.w;
                s[3][0] += qv.w*kv.x; s[3][1] += qv.w*kv.y; s[3][2] += qv.w*kv.z; s[3][3] += qv.w*kv.w;
            }
        }

        // ---- online softmax (per-row state in registers, half-warp shfl) ----
        const float scale = 0.0625f;   // 1/sqrt(256)
        #pragma unroll
        for (int i = 0; i < 4; i++) {
            #pragma unroll
            for (int j = 0; j < 4; j++) {
                s[i][j] *= scale;
                if (k0 + tx*4 + j >= len) s[i][j] = -1e30f;
            }
            float mx = fmaxf(fmaxf(s[i][0], s[i][1]), fmaxf(s[i][2], s[i][3]));
            mx = fmaxf(mx, __shfl_xor_sync(0xffffffffu, mx, 1));
            mx = fmaxf(mx, __shfl_xor_sync(0xffffffffu, mx, 2));
            mx = fmaxf(mx, __shfl_xor_sync(0xffffffffu, mx, 4));
            mx = fmaxf(mx, __shfl_xor_sync(0xffffffffu, mx, 8));

            float mnew  = fmaxf(mrow[i], mx);
            float alpha = __expf(mrow[i] - mnew);
            mrow[i] = mnew;

            float rs = 0.f;
            #pragma unroll
            for (int j = 0; j < 4; j++) {
                float p = __expf(s[i][j] - mnew);
                s[i][j] = p;
                rs += p;
            }
            rs += __shfl_xor_sync(0xffffffffu, rs, 1);
            rs += __shfl_xor_sync(0xffffffffu, rs, 2);
            rs += __shfl_xor_sync(0xffffffffu, rs, 4);
            rs += __shfl_xor_sync(0xffffffffu, rs, 8);
            lrow[i] = lrow[i] * alpha + rs;

            #pragma unroll
            for (int j2 = 0; j2 < 16; j2++) acc[i][j2] *= alpha;

            *(float4*)&sP[(ty*4 + i)*64 + tx*4] =
                make_float4(s[i][0], s[i][1], s[i][2], s[i][3]);
        }
        __syncthreads();   // sP visible; S-phase done reading sKV

        // ---- O += P V over two 128-wide d-chunks ----
        #pragma unroll
        for (int ch = 0; ch < 2; ch++) {
            // load V chunk row-major [64][128] (coalesced, conflict-free)
            #pragma unroll
            for (int it = 0; it < 8; it++) {
                int v  = tid + it * 256;
                int c  = v >> 5;
                int d4 = v & 31;
                *(float4*)&sKV[c*128 + d4*4] =
                    *(const float4*)&gVb[(k0 + c) * HH + ch*128 + d4*4];
            }
            __syncthreads();

            #pragma unroll 4
            for (int cg = 0; cg < 16; cg++) {
                float pr[4][4];
                #pragma unroll
                for (int i = 0; i < 4; i++) {
                    float4 t = *(const float4*)&sP[(ty*4 + i)*64 + cg*4];
                    pr[i][0] = t.x; pr[i][1] = t.y; pr[i][2] = t.z; pr[i][3] = t.w;
                }
                #pragma unroll
                for (int j4 = 0; j4 < 4; j4++) {
                    int c = cg*4 + j4;
                    #pragma unroll
                    for (int half = 0; half < 2; half++) {
                        float4 v = *(const float4*)&sKV[c*128 + half*64 + tx*4];
                        int cb = (ch*2 + half) * 4;
                        #pragma unroll
                        for (int i = 0; i < 4; i++) {
                            acc[i][cb+0] += pr[i][j4] * v.x;
                            acc[i][cb+1] += pr[i][j4] * v.y;
                            acc[i][cb+2] += pr[i][j4] * v.z;
                            acc[i][cb+3] += pr[i][j4] * v.w;
                        }
                    }
                }
            }
            __syncthreads();   // done reading this V chunk; sKV reusable
        }
    }

    // ---- epilogue: out = acc / l ----
    #pragma unroll
    for (int i = 0; i < 4; i++) {
        float inv = 1.f / lrow[i];
        int q = q0 + ty*4 + i;
        float* orow = out + (b * LL + q) * HH;
        #pragma unroll
        for (int c2 = 0; c2 < 4; c2++) {
            int d = (c2 >> 1) * 128 + (c2 & 1) * 64 + tx*4;
            float4 o = make_float4(acc[i][c2*4+0] * inv, acc[i][c2*4+1] * inv,
                                   acc[i][c2*4+2] * inv, acc[i][c2*4+3] * inv);
            *(float4*)&orow[d] = o;
        }
    }
}

// ---------------------------------------------------------------------------
extern "C" void kernel_launch(void* const* d_in, const int* in_sizes, int n_in,
                              void* d_out, int out_size)
{
    const float* X   = (const float*)d_in[0];
    const float* Wq  = (const float*)d_in[1];
    const float* Wk  = (const float*)d_in[2];
    const float* Wv  = (const float*)d_in[3];
    const int*   lens = (const int*)d_in[4];
    float* out = (float*)d_out;

    qkv_kernel<<<dim3(4, 256, 3), 256>>>(X, Wq, Wk, Wv);

    cudaFuncSetAttribute(attn_kernel,
                         cudaFuncAttributeMaxDynamicSharedMemorySize, 114688);
    attn_kernel<<<dim3(LL / 64, BB), 256, 114688>>>(lens, out);
}

// round 3
// speedup vs baseline: 2.4541x; 2.4541x over previous
#include <cuda_runtime.h>
#include <cuda_bf16.h>
#include <math.h>

#define BB 8
#define LL 2048
#define HH 256
#define MTOT (BB*LL)

// bf16 split (hi/lo) projected tensors, all row-major [b*L][H].
__device__ __nv_bfloat16 g_Qh[MTOT*HH];
__device__ __nv_bfloat16 g_Ql[MTOT*HH];
__device__ __nv_bfloat16 g_Kh[MTOT*HH];
__device__ __nv_bfloat16 g_Kl[MTOT*HH];
__device__ __nv_bfloat16 g_Vh[MTOT*HH];
__device__ __nv_bfloat16 g_Vl[MTOT*HH];

// ---------------- helpers ----------------
__device__ __forceinline__ unsigned smem_u32(const void* p) {
    unsigned a;
    asm("{ .reg .u64 t; cvta.to.shared.u64 t, %1; cvt.u32.u64 %0, t; }" : "=r"(a) : "l"(p));
    return a;
}
__device__ __forceinline__ unsigned packbf2(float e0, float e1) {
    unsigned r;  // low half = e0, high half = e1
    asm("cvt.rn.bf16x2.f32 %0, %1, %2;" : "=r"(r) : "f"(e1), "f"(e0));
    return r;
}
__device__ __forceinline__ void ldsm4(unsigned* r, unsigned addr) {
    asm volatile("ldmatrix.sync.aligned.m8n8.x4.shared.b16 {%0,%1,%2,%3}, [%4];"
                 : "=r"(r[0]), "=r"(r[1]), "=r"(r[2]), "=r"(r[3]) : "r"(addr));
}
__device__ __forceinline__ void ldsm4t(unsigned* r, unsigned addr) {
    asm volatile("ldmatrix.sync.aligned.m8n8.x4.trans.shared.b16 {%0,%1,%2,%3}, [%4];"
                 : "=r"(r[0]), "=r"(r[1]), "=r"(r[2]), "=r"(r[3]) : "r"(addr));
}
__device__ __forceinline__ void mma16816(float* c, const unsigned* a, unsigned b0, unsigned b1) {
    asm volatile(
        "mma.sync.aligned.m16n8k16.row.col.f32.bf16.bf16.f32 "
        "{%0,%1,%2,%3},{%4,%5,%6,%7},{%8,%9},{%0,%1,%2,%3};"
        : "+f"(c[0]), "+f"(c[1]), "+f"(c[2]), "+f"(c[3])
        : "r"(a[0]), "r"(a[1]), "r"(a[2]), "r"(a[3]), "r"(b0), "r"(b1));
}

// smem tile layout: rows of 256 bf16 = 512B = 32 16B-chunks, XOR swizzle.
__device__ __forceinline__ unsigned tswz(int r, int c8) {
    return (unsigned)(r * 512 + ((c8 ^ (r & 7)) << 4));
}

#define SM_QH 0
#define SM_QL 65536
#define SM_KH 131072
#define SM_KL 163840
#define SMEM_TOTAL 196608

// ---------------------------------------------------------------------------
// QKV projection (fp32 SIMT), emitting bf16 hi/lo splits, row-major.
// ---------------------------------------------------------------------------
__global__ __launch_bounds__(256) void qkv_kernel(
    const float* __restrict__ X,
    const float* __restrict__ Wq,
    const float* __restrict__ Wk,
    const float* __restrict__ Wv)
{
    __shared__ float sA[16][64];
    __shared__ float sB[16][64];

    const float* W;
    __nv_bfloat16 *Yh, *Yl;
    if (blockIdx.z == 0)      { W = Wq; Yh = g_Qh; Yl = g_Ql; }
    else if (blockIdx.z == 1) { W = Wk; Yh = g_Kh; Yl = g_Kl; }
    else                      { W = Wv; Yh = g_Vh; Yl = g_Vl; }

    const int m0  = blockIdx.y * 64;
    const int n0  = blockIdx.x * 64;
    const int tid = threadIdx.x;
    const int row = tid >> 2;
    const int kq  = tid & 3;
    const int ty  = tid >> 4;
    const int tx  = tid & 15;

    float c[4][4] = {};

    for (int kc = 0; kc < HH; kc += 16) {
        float4 a  = *(const float4*)&X[(m0 + row) * HH + kc + kq * 4];
        float4 bv = *(const float4*)&W[(n0 + row) * HH + kc + kq * 4];
        __syncthreads();
        sA[kq*4+0][row] = a.x;  sA[kq*4+1][row] = a.y;
        sA[kq*4+2][row] = a.z;  sA[kq*4+3][row] = a.w;
        sB[kq*4+0][row] = bv.x; sB[kq*4+1][row] = bv.y;
        sB[kq*4+2][row] = bv.z; sB[kq*4+3][row] = bv.w;
        __syncthreads();

        #pragma unroll
        for (int kk = 0; kk < 16; kk++) {
            float4 av = *(const float4*)&sA[kk][ty * 4];
            float4 bw = *(const float4*)&sB[kk][tx * 4];
            c[0][0] += av.x * bw.x; c[0][1] += av.x * bw.y; c[0][2] += av.x * bw.z; c[0][3] += av.x * bw.w;
            c[1][0] += av.y * bw.x; c[1][1] += av.y * bw.y; c[1][2] += av.y * bw.z; c[1][3] += av.y * bw.w;
            c[2][0] += av.z * bw.x; c[2][1] += av.z * bw.y; c[2][2] += av.z * bw.z; c[2][3] += av.z * bw.w;
            c[3][0] += av.w * bw.x; c[3][1] += av.w * bw.y; c[3][2] += av.w * bw.z; c[3][3] += av.w * bw.w;
        }
    }

    #pragma unroll
    for (int i = 0; i < 4; i++) {
        size_t base = (size_t)(m0 + ty*4 + i) * HH + n0 + tx*4;
        unsigned* dh = (unsigned*)(Yh + base);
        unsigned* dl = (unsigned*)(Yl + base);
        #pragma unroll
        for (int p = 0; p < 2; p++) {
            float x0 = c[i][2*p], x1 = c[i][2*p+1];
            unsigned wh = packbf2(x0, x1);
            float r0 = x0 - __uint_as_float(wh << 16);
            float r1 = x1 - __uint_as_float(wh & 0xFFFF0000u);
            dh[p] = wh;
            dl[p] = packbf2(r0, r1);
        }
    }
}

// ---------------------------------------------------------------------------
// mma.sync flash attention, no-max softmax, bf16x3.
// CTA: 128 queries x batch; 8 warps x 16 q-rows; 64-key tiles; d=256.
// ---------------------------------------------------------------------------
__global__ __launch_bounds__(256, 1) void attn_kernel(
    const int* __restrict__ lens,
    float* __restrict__ out)
{
    extern __shared__ char smc[];
    const unsigned sb = smem_u32(smc);
    const int tid = threadIdx.x;
    const int w   = tid >> 5;
    const int l   = tid & 31;
    const int b   = blockIdx.y;
    const int q0  = blockIdx.x * 128;
    const int len = lens[b];

    // ---- load Q hi/lo (swizzled) ----
    {
        const __nv_bfloat16* qh = g_Qh + (size_t)(b * LL + q0) * HH;
        const __nv_bfloat16* ql = g_Ql + (size_t)(b * LL + q0) * HH;
        #pragma unroll
        for (int it = 0; it < 16; it++) {
            int v = tid + it * 256;
            int r = v >> 5, c8 = v & 31;
            unsigned off = tswz(r, c8);
            *(uint4*)(smc + SM_QH + off) = *(const uint4*)(qh + r * HH + c8 * 8);
            *(uint4*)(smc + SM_QL + off) = *(const uint4*)(ql + r * HH + c8 * 8);
        }
    }

    float o[32][4];
    #pragma unroll
    for (int n = 0; n < 32; n++)
        #pragma unroll
        for (int e = 0; e < 4; e++) o[n][e] = 0.f;
    float rs0 = 0.f, rs1 = 0.f;

    // lane constants
    const int qrow = (w << 4) + (l & 15);          // A-frag row
    const int qx   = l >> 4;                       // A-frag chunk parity
    const int qsw  = qrow & 7;
    const unsigned qbH = SM_QH + (unsigned)qrow * 512;
    const unsigned qbL = SM_QL + (unsigned)qrow * 512;
    const int krl  = ((l & 16) >> 1) + (l & 7);    // K B-frag row offset
    const int kcp  = (l >> 3) & 1;                 // K B-frag chunk parity
    const int vrl  = (((l >> 3) & 1) << 3) + (l & 7); // V B-frag row offset
    const int vco  = l >> 4;                       // V B-frag chunk parity

    const float SC = 0.0625f;  // 1/sqrt(256)
    const int nkt = (len + 63) >> 6;

    for (int kt = 0; kt < nkt; kt++) {
        const int k0 = kt << 6;

        // ---- load K tile hi/lo ----
        {
            const __nv_bfloat16* kh = g_Kh + (size_t)(b * LL + k0) * HH;
            const __nv_bfloat16* kl = g_Kl + (size_t)(b * LL + k0) * HH;
            #pragma unroll
            for (int it = 0; it < 8; it++) {
                int v = tid + it * 256;
                int r = v >> 5, c8 = v & 31;
                unsigned off = tswz(r, c8);
                *(uint4*)(smc + SM_KH + off) = *(const uint4*)(kh + r * HH + c8 * 8);
                *(uint4*)(smc + SM_KL + off) = *(const uint4*)(kl + r * HH + c8 * 8);
            }
        }
        __syncthreads();

        // ---- S = Q K^T (3 passes) ----
        float s[8][4];
        #pragma unroll
        for (int j = 0; j < 8; j++)
            #pragma unroll
            for (int e = 0; e < 4; e++) s[j][e] = 0.f;

        #pragma unroll 4
        for (int ks = 0; ks < 16; ks++) {
            unsigned ah[4], al[4];
            int ach = 2 * ks + qx;
            ldsm4(ah, sb + qbH + ((unsigned)((ach ^ qsw) << 4)));
            ldsm4(al, sb + qbL + ((unsigned)((ach ^ qsw) << 4)));
            #pragma unroll
            for (int j2 = 0; j2 < 4; j2++) {
                int br = (j2 << 4) + krl;
                int bch = 2 * ks + kcp;
                unsigned boff = tswz(br, bch);
                unsigned bh[4], bl[4];
                ldsm4(bh, sb + SM_KH + boff);
                ldsm4(bl, sb + SM_KL + boff);
                mma16816(s[2*j2],   ah, bh[0], bh[1]);
                mma16816(s[2*j2],   ah, bl[0], bl[1]);
                mma16816(s[2*j2],   al, bh[0], bh[1]);
                mma16816(s[2*j2+1], ah, bh[2], bh[3]);
                mma16816(s[2*j2+1], ah, bl[2], bl[3]);
                mma16816(s[2*j2+1], al, bh[2], bh[3]);
            }
        }
        __syncthreads();   // all warps done reading K

        // ---- load V tile hi/lo into same buffers ----
        {
            const __nv_bfloat16* vh = g_Vh + (size_t)(b * LL + k0) * HH;
            const __nv_bfloat16* vl = g_Vl + (size_t)(b * LL + k0) * HH;
            #pragma unroll
            for (int it = 0; it < 8; it++) {
                int v = tid + it * 256;
                int r = v >> 5, c8 = v & 31;
                unsigned off = tswz(r, c8);
                *(uint4*)(smc + SM_KH + off) = *(const uint4*)(vh + r * HH + c8 * 8);
                *(uint4*)(smc + SM_KL + off) = *(const uint4*)(vl + r * HH + c8 * 8);
            }
        }

        // ---- softmax (registers only; overlaps V LDG latency) ----
        unsigned aph[4][4], apl[4][4];
        #pragma unroll
        for (int kk = 0; kk < 4; kk++) {
            #pragma unroll
            for (int h = 0; h < 2; h++) {
                int j = 2 * kk + h;
                int col = k0 + 8 * j + 2 * (l & 3);
                float p0 = (col     < len) ? __expf(s[j][0] * SC) : 0.f;
                float p1 = (col + 1 < len) ? __expf(s[j][1] * SC) : 0.f;
                float p2 = (col     < len) ? __expf(s[j][2] * SC) : 0.f;
                float p3 = (col + 1 < len) ? __expf(s[j][3] * SC) : 0.f;
                rs0 += p0 + p1;
                rs1 += p2 + p3;
                unsigned h01 = packbf2(p0, p1);
                unsigned h23 = packbf2(p2, p3);
                aph[kk][2*h+0] = h01;
                aph[kk][2*h+1] = h23;
                float r0 = p0 - __uint_as_float(h01 << 16);
                float r1 = p1 - __uint_as_float(h01 & 0xFFFF0000u);
                float r2 = p2 - __uint_as_float(h23 << 16);
                float r3 = p3 - __uint_as_float(h23 & 0xFFFF0000u);
                apl[kk][2*h+0] = packbf2(r0, r1);
                apl[kk][2*h+1] = packbf2(r2, r3);
            }
        }
        __syncthreads();   // V tile visible

        // ---- O += P V (3 passes) ----
        #pragma unroll
        for (int kk = 0; kk < 4; kk++) {
            #pragma unroll
            for (int j2 = 0; j2 < 16; j2++) {
                int vr = (kk << 4) + vrl;
                int vch = 2 * j2 + vco;
                unsigned voff = tswz(vr, vch);
                unsigned bh[4], bl[4];
                ldsm4t(bh, sb + SM_KH + voff);
                ldsm4t(bl, sb + SM_KL + voff);
                mma16816(o[2*j2],   aph[kk], bh[0], bh[1]);
                mma16816(o[2*j2],   aph[kk], bl[0], bl[1]);
                mma16816(o[2*j2],   apl[kk], bh[0], bh[1]);
                mma16816(o[2*j2+1], aph[kk], bh[2], bh[3]);
                mma16816(o[2*j2+1], aph[kk], bl[2], bl[3]);
                mma16816(o[2*j2+1], apl[kk], bh[2], bh[3]);
            }
        }
        __syncthreads();   // done reading V before next K load
    }

    // ---- epilogue ----
    rs0 += __shfl_xor_sync(0xffffffffu, rs0, 1);
    rs0 += __shfl_xor_sync(0xffffffffu, rs0, 2);
    rs1 += __shfl_xor_sync(0xffffffffu, rs1, 1);
    rs1 += __shfl_xor_sync(0xffffffffu, rs1, 2);
    const float inv0 = 1.f / rs0;
    const float inv1 = 1.f / rs1;

    const int row0 = q0 + (w << 4) + (l >> 2);
    const int row1 = row0 + 8;
    const int colb = 2 * (l & 3);
    float* o0 = out + (size_t)(b * LL + row0) * HH + colb;
    float* o1 = out + (size_t)(b * LL + row1) * HH + colb;
    #pragma unroll
    for (int n = 0; n < 32; n++) {
        *(float2*)(o0 + 8 * n) = make_float2(o[n][0] * inv0, o[n][1] * inv0);
        *(float2*)(o1 + 8 * n) = make_float2(o[n][2] * inv1, o[n][3] * inv1);
    }
}

// ---------------------------------------------------------------------------
extern "C" void kernel_launch(void* const* d_in, const int* in_sizes, int n_in,
                              void* d_out, int out_size)
{
    const float* X    = (const float*)d_in[0];
    const float* Wq   = (const float*)d_in[1];
    const float* Wk   = (const float*)d_in[2];
    const float* Wv   = (const float*)d_in[3];
    const int*   lens = (const int*)d_in[4];
    float* out = (float*)d_out;

    qkv_kernel<<<dim3(4, 256, 3), 256>>>(X, Wq, Wk, Wv);

    cudaFuncSetAttribute(attn_kernel,
                         cudaFuncAttributeMaxDynamicSharedMemorySize, SMEM_TOTAL);
    attn_kernel<<<dim3(LL / 128, BB), 256, SMEM_TOTAL>>>(lens, out);
}

// round 5
// speedup vs baseline: 3.7021x; 1.5085x over previous
#include <cuda_runtime.h>
#include <cuda_bf16.h>
#include <math.h>

#define BB 8
#define LL 2048
#define HH 256
#define MTOT (BB*LL)

// bf16 split (hi/lo) projected tensors, all row-major [b*L][H].
__device__ __align__(16) __nv_bfloat16 g_Qh[MTOT*HH];
__device__ __align__(16) __nv_bfloat16 g_Ql[MTOT*HH];
__device__ __align__(16) __nv_bfloat16 g_Kh[MTOT*HH];
__device__ __align__(16) __nv_bfloat16 g_Kl[MTOT*HH];
__device__ __align__(16) __nv_bfloat16 g_Vh[MTOT*HH];
__device__ __align__(16) __nv_bfloat16 g_Vl[MTOT*HH];

// ---------------- helpers ----------------
__device__ __forceinline__ unsigned smem_u32(const void* p) {
    unsigned a;
    asm("{ .reg .u64 t; cvta.to.shared.u64 t, %1; cvt.u32.u64 %0, t; }" : "=r"(a) : "l"(p));
    return a;
}
__device__ __forceinline__ unsigned packbf2(float e0, float e1) {
    unsigned r;  // low half = e0, high half = e1
    asm("cvt.rn.bf16x2.f32 %0, %1, %2;" : "=r"(r) : "f"(e1), "f"(e0));
    return r;
}
__device__ __forceinline__ void ldsm4(unsigned* r, unsigned addr) {
    asm volatile("ldmatrix.sync.aligned.m8n8.x4.shared.b16 {%0,%1,%2,%3}, [%4];"
                 : "=r"(r[0]), "=r"(r[1]), "=r"(r[2]), "=r"(r[3]) : "r"(addr));
}
__device__ __forceinline__ void ldsm4t(unsigned* r, unsigned addr) {
    asm volatile("ldmatrix.sync.aligned.m8n8.x4.trans.shared.b16 {%0,%1,%2,%3}, [%4];"
                 : "=r"(r[0]), "=r"(r[1]), "=r"(r[2]), "=r"(r[3]) : "r"(addr));
}
__device__ __forceinline__ void mma16816(float* c, const unsigned* a, unsigned b0, unsigned b1) {
    asm volatile(
        "mma.sync.aligned.m16n8k16.row.col.f32.bf16.bf16.f32 "
        "{%0,%1,%2,%3},{%4,%5,%6,%7},{%8,%9},{%0,%1,%2,%3};"
        : "+f"(c[0]), "+f"(c[1]), "+f"(c[2]), "+f"(c[3])
        : "r"(a[0]), "r"(a[1]), "r"(a[2]), "r"(a[3]), "r"(b0), "r"(b1));
}
__device__ __forceinline__ void cp16(unsigned dst, const void* src) {
    asm volatile("cp.async.cg.shared.global [%0], [%1], 16;" :: "r"(dst), "l"(src) : "memory");
}
__device__ __forceinline__ void cp_commit() { asm volatile("cp.async.commit_group;" ::: "memory"); }
__device__ __forceinline__ void cp_wait0()  { asm volatile("cp.async.wait_group 0;"  ::: "memory"); }

// smem tile layout: rows of 256 bf16 = 512B = 32 16B-chunks, XOR swizzle.
__device__ __forceinline__ unsigned tswz(int r, int c8) {
    return (unsigned)(r * 512 + ((c8 ^ (r & 7)) << 4));
}

#define SM_QH 0
#define SM_QL 65536
#define SM_KH 131072
#define SM_KL 163840
#define SMEM_TOTAL 196608

// qkv_mma smem layout
#define SM_XH 0
#define SM_XL 65536
#define SM_WH 131072
#define SM_WL 163840

// ---------------------------------------------------------------------------
// QKV projection on tensor cores (bf16 hi/lo x3 passes).
// CTA = 128 X-rows; X tile converted once, reused for 3 weights x 4 n-tiles.
// ---------------------------------------------------------------------------
__global__ __launch_bounds__(256, 1) void qkv_mma_kernel(
    const float* __restrict__ X,
    const float* __restrict__ Wq,
    const float* __restrict__ Wk,
    const float* __restrict__ Wv)
{
    extern __shared__ char smc[];
    const unsigned sb = smem_u32(smc);
    const int tid = threadIdx.x;
    const int w   = tid >> 5;
    const int l   = tid & 31;
    const int m0  = blockIdx.x * 128;

    // ---- X tile -> bf16 hi/lo, swizzled ----
    #pragma unroll
    for (int it = 0; it < 16; it++) {
        int v = tid + it * 256;
        int r = v >> 5, c8 = v & 31;
        const float* src = X + (size_t)(m0 + r) * HH + c8 * 8;
        float4 a = *(const float4*)src;
        float4 c = *(const float4*)(src + 4);
        unsigned h0 = packbf2(a.x, a.y), h1 = packbf2(a.z, a.w);
        unsigned h2 = packbf2(c.x, c.y), h3 = packbf2(c.z, c.w);
        unsigned l0 = packbf2(a.x - __uint_as_float(h0 << 16), a.y - __uint_as_float(h0 & 0xFFFF0000u));
        unsigned l1 = packbf2(a.z - __uint_as_float(h1 << 16), a.w - __uint_as_float(h1 & 0xFFFF0000u));
        unsigned l2 = packbf2(c.x - __uint_as_float(h2 << 16), c.y - __uint_as_float(h2 & 0xFFFF0000u));
        unsigned l3 = packbf2(c.z - __uint_as_float(h3 << 16), c.w - __uint_as_float(h3 & 0xFFFF0000u));
        unsigned off = tswz(r, c8);
        *(uint4*)(smc + SM_XH + off) = make_uint4(h0, h1, h2, h3);
        *(uint4*)(smc + SM_XL + off) = make_uint4(l0, l1, l2, l3);
    }
    __syncthreads();

    // lane constants (same fragment scheme as attention)
    const int qrow = (w << 4) + (l & 15);
    const int qx   = l >> 4;
    const int qsw  = qrow & 7;
    const unsigned xbH = SM_XH + (unsigned)qrow * 512;
    const unsigned xbL = SM_XL + (unsigned)qrow * 512;
    const int krl  = ((l & 16) >> 1) + (l & 7);
    const int kcp  = (l >> 3) & 1;

    #pragma unroll 1
    for (int z = 0; z < 3; z++) {
        const float* W = (z == 0) ? Wq : (z == 1) ? Wk : Wv;
        __nv_bfloat16* Yh = (z == 0) ? g_Qh : (z == 1) ? g_Kh : g_Vh;
        __nv_bfloat16* Yl = (z == 0) ? g_Ql : (z == 1) ? g_Kl : g_Vl;

        #pragma unroll 1
        for (int nt = 0; nt < 4; nt++) {
            // ---- W tile (64 out-rows x 256) -> bf16 hi/lo swizzled ----
            #pragma unroll
            for (int it = 0; it < 8; it++) {
                int v = tid + it * 256;
                int r = v >> 5, c8 = v & 31;
                const float* src = W + (size_t)(nt * 64 + r) * HH + c8 * 8;
                float4 a = *(const float4*)src;
                float4 c = *(const float4*)(src + 4);
                unsigned h0 = packbf2(a.x, a.y), h1 = packbf2(a.z, a.w);
                unsigned h2 = packbf2(c.x, c.y), h3 = packbf2(c.z, c.w);
                unsigned l0 = packbf2(a.x - __uint_as_float(h0 << 16), a.y - __uint_as_float(h0 & 0xFFFF0000u));
                unsigned l1 = packbf2(a.z - __uint_as_float(h1 << 16), a.w - __uint_as_float(h1 & 0xFFFF0000u));
                unsigned l2 = packbf2(c.x - __uint_as_float(h2 << 16), c.y - __uint_as_float(h2 & 0xFFFF0000u));
                unsigned l3 = packbf2(c.z - __uint_as_float(h3 << 16), c.w - __uint_as_float(h3 & 0xFFFF0000u));
                unsigned off = tswz(r, c8);
                *(uint4*)(smc + SM_WH + off) = make_uint4(h0, h1, h2, h3);
                *(uint4*)(smc + SM_WL + off) = make_uint4(l0, l1, l2, l3);
            }
            __syncthreads();

            float c[8][4];
            #pragma unroll
            for (int j = 0; j < 8; j++)
                #pragma unroll
                for (int e = 0; e < 4; e++) c[j][e] = 0.f;

            #pragma unroll 4
            for (int ks = 0; ks < 16; ks++) {
                unsigned ah[4], al[4];
                int ach = 2 * ks + qx;
                ldsm4(ah, sb + xbH + ((unsigned)((ach ^ qsw) << 4)));
                ldsm4(al, sb + xbL + ((unsigned)((ach ^ qsw) << 4)));
                #pragma unroll
                for (int j2 = 0; j2 < 4; j2++) {
                    unsigned boff = tswz((j2 << 4) + krl, 2 * ks + kcp);
                    unsigned bh[4], bl[4];
                    ldsm4(bh, sb + SM_WH + boff);
                    ldsm4(bl, sb + SM_WL + boff);
                    mma16816(c[2*j2],   ah, bh[0], bh[1]);
                    mma16816(c[2*j2],   ah, bl[0], bl[1]);
                    mma16816(c[2*j2],   al, bh[0], bh[1]);
                    mma16816(c[2*j2+1], ah, bh[2], bh[3]);
                    mma16816(c[2*j2+1], ah, bl[2], bl[3]);
                    mma16816(c[2*j2+1], al, bh[2], bh[3]);
                }
            }
            __syncthreads();   // done reading W tile before next overwrite

            // ---- epilogue: split each fp32 result into bf16 hi/lo ----
            const int row0 = m0 + (w << 4) + (l >> 2);
            const int col  = nt * 64 + 2 * (l & 3);
            #pragma unroll
            for (int j = 0; j < 8; j++) {
                size_t base0 = (size_t)row0 * HH + col + j * 8;
                size_t base1 = base0 + (size_t)8 * HH;
                unsigned h01 = packbf2(c[j][0], c[j][1]);
                unsigned l01 = packbf2(c[j][0] - __uint_as_float(h01 << 16),
                                       c[j][1] - __uint_as_float(h01 & 0xFFFF0000u));
                unsigned h23 = packbf2(c[j][2], c[j][3]);
                unsigned l23 = packbf2(c[j][2] - __uint_as_float(h23 << 16),
                                       c[j][3] - __uint_as_float(h23 & 0xFFFF0000u));
                *(unsigned*)(Yh + base0) = h01;
                *(unsigned*)(Yl + base0) = l01;
                *(unsigned*)(Yh + base1) = h23;
                *(unsigned*)(Yl + base1) = l23;
            }
        }
    }
}

// ---------------------------------------------------------------------------
// mma.sync flash attention, no-max softmax, bf16x3, cp.async loads.
// CTA: 128 queries x batch; 8 warps x 16 q-rows; 64-key tiles; d=256.
// ---------------------------------------------------------------------------
__global__ __launch_bounds__(256, 1) void attn_kernel(
    const int* __restrict__ lens,
    float* __restrict__ out)
{
    extern __shared__ char smc[];
    const unsigned sb = smem_u32(smc);
    const int tid = threadIdx.x;
    const int w   = tid >> 5;
    const int l   = tid & 31;
    const int b   = blockIdx.y;
    const int q0  = blockIdx.x * 128;
    const int len = lens[b];

    // ---- load Q hi/lo (swizzled) via cp.async; wait folded into first K wait ----
    {
        const __nv_bfloat16* qh = g_Qh + (size_t)(b * LL + q0) * HH;
        const __nv_bfloat16* ql = g_Ql + (size_t)(b * LL + q0) * HH;
        #pragma unroll
        for (int it = 0; it < 16; it++) {
            int v = tid + it * 256;
            int r = v >> 5, c8 = v & 31;
            unsigned off = tswz(r, c8);
            cp16(sb + SM_QH + off, qh + r * HH + c8 * 8);
            cp16(sb + SM_QL + off, ql + r * HH + c8 * 8);
        }
        cp_commit();
    }

    float o[32][4];
    #pragma unroll
    for (int n = 0; n < 32; n++)
        #pragma unroll
        for (int e = 0; e < 4; e++) o[n][e] = 0.f;
    float rs0 = 0.f, rs1 = 0.f;

    // lane constants
    const int qrow = (w << 4) + (l & 15);
    const int qx   = l >> 4;
    const int qsw  = qrow & 7;
    const unsigned qbH = SM_QH + (unsigned)qrow * 512;
    const unsigned qbL = SM_QL + (unsigned)qrow * 512;
    const int krl  = ((l & 16) >> 1) + (l & 7);
    const int kcp  = (l >> 3) & 1;
    const int vrl  = (((l >> 3) & 1) << 3) + (l & 7);
    const int vco  = l >> 4;

    const float SC = 0.0625f;  // 1/sqrt(256)
    const int nkt = (len + 63) >> 6;

    for (int kt = 0; kt < nkt; kt++) {
        const int k0 = kt << 6;

        // ---- K tile hi/lo via cp.async ----
        {
            const __nv_bfloat16* kh = g_Kh + (size_t)(b * LL + k0) * HH;
            const __nv_bfloat16* kl = g_Kl + (size_t)(b * LL + k0) * HH;
            #pragma unroll
            for (int it = 0; it < 8; it++) {
                int v = tid + it * 256;
                int r = v >> 5, c8 = v & 31;
                unsigned off = tswz(r, c8);
                cp16(sb + SM_KH + off, kh + r * HH + c8 * 8);
                cp16(sb + SM_KL + off, kl + r * HH + c8 * 8);
            }
            cp_commit();
            cp_wait0();
        }
        __syncthreads();

        // ---- S = Q K^T (3 passes) ----
        float s[8][4];
        #pragma unroll
        for (int j = 0; j < 8; j++)
            #pragma unroll
            for (int e = 0; e < 4; e++) s[j][e] = 0.f;

        #pragma unroll 4
        for (int ks = 0; ks < 16; ks++) {
            unsigned ah[4], al[4];
            int ach = 2 * ks + qx;
            ldsm4(ah, sb + qbH + ((unsigned)((ach ^ qsw) << 4)));
            ldsm4(al, sb + qbL + ((unsigned)((ach ^ qsw) << 4)));
            #pragma unroll
            for (int j2 = 0; j2 < 4; j2++) {
                unsigned boff = tswz((j2 << 4) + krl, 2 * ks + kcp);
                unsigned bh[4], bl[4];
                ldsm4(bh, sb + SM_KH + boff);
                ldsm4(bl, sb + SM_KL + boff);
                mma16816(s[2*j2],   ah, bh[0], bh[1]);
                mma16816(s[2*j2],   ah, bl[0], bl[1]);
                mma16816(s[2*j2],   al, bh[0], bh[1]);
                mma16816(s[2*j2+1], ah, bh[2], bh[3]);
                mma16816(s[2*j2+1], ah, bl[2], bl[3]);
                mma16816(s[2*j2+1], al, bh[2], bh[3]);
            }
        }
        __syncthreads();   // all warps done reading K

        // ---- V tile hi/lo via cp.async (no wait yet; overlaps softmax) ----
        {
            const __nv_bfloat16* vh = g_Vh + (size_t)(b * LL + k0) * HH;
            const __nv_bfloat16* vl = g_Vl + (size_t)(b * LL + k0) * HH;
            #pragma unroll
            for (int it = 0; it < 8; it++) {
                int v = tid + it * 256;
                int r = v >> 5, c8 = v & 31;
                unsigned off = tswz(r, c8);
                cp16(sb + SM_KH + off, vh + r * HH + c8 * 8);
                cp16(sb + SM_KL + off, vl + r * HH + c8 * 8);
            }
            cp_commit();
        }

        // ---- softmax in registers (tile-level mask hoist) ----
        unsigned aph[4][4], apl[4][4];
        if (k0 + 64 <= len) {
            #pragma unroll
            for (int kk = 0; kk < 4; kk++) {
                #pragma unroll
                for (int h = 0; h < 2; h++) {
                    int j = 2 * kk + h;
                    float p0 = __expf(s[j][0] * SC);
                    float p1 = __expf(s[j][1] * SC);
                    float p2 = __expf(s[j][2] * SC);
                    float p3 = __expf(s[j][3] * SC);
                    rs0 += p0 + p1;
                    rs1 += p2 + p3;
                    unsigned h01 = packbf2(p0, p1);
                    unsigned h23 = packbf2(p2, p3);
                    aph[kk][2*h+0] = h01;
                    aph[kk][2*h+1] = h23;
                    apl[kk][2*h+0] = packbf2(p0 - __uint_as_float(h01 << 16),
                                             p1 - __uint_as_float(h01 & 0xFFFF0000u));
                    apl[kk][2*h+1] = packbf2(p2 - __uint_as_float(h23 << 16),
                                             p3 - __uint_as_float(h23 & 0xFFFF0000u));
                }
            }
        } else {
            #pragma unroll
            for (int kk = 0; kk < 4; kk++) {
                #pragma unroll
                for (int h = 0; h < 2; h++) {
                    int j = 2 * kk + h;
                    int col = k0 + 8 * j + 2 * (l & 3);
                    float p0 = (col     < len) ? __expf(s[j][0] * SC) : 0.f;
                    float p1 = (col + 1 < len) ? __expf(s[j][1] * SC) : 0.f;
                    float p2 = (col     < len) ? __expf(s[j][2] * SC) : 0.f;
                    float p3 = (col + 1 < len) ? __expf(s[j][3] * SC) : 0.f;
                    rs0 += p0 + p1;
                    rs1 += p2 + p3;
                    unsigned h01 = packbf2(p0, p1);
                    unsigned h23 = packbf2(p2, p3);
                    aph[kk][2*h+0] = h01;
                    aph[kk][2*h+1] = h23;
                    apl[kk][2*h+0] = packbf2(p0 - __uint_as_float(h01 << 16),
                                             p1 - __uint_as_float(h01 & 0xFFFF0000u));
                    apl[kk][2*h+1] = packbf2(p2 - __uint_as_float(h23 << 16),
                                             p3 - __uint_as_float(h23 & 0xFFFF0000u));
                }
            }
        }
        cp_wait0();
        __syncthreads();   // V tile visible

        // ---- O += P V (3 passes) ----
        #pragma unroll
        for (int kk = 0; kk < 4; kk++) {
            #pragma unroll
            for (int j2 = 0; j2 < 16; j2++) {
                unsigned voff = tswz((kk << 4) + vrl, 2 * j2 + vco);
                unsigned bh[4], bl[4];
                ldsm4t(bh, sb + SM_KH + voff);
                ldsm4t(bl, sb + SM_KL + voff);
                mma16816(o[2*j2],   aph[kk], bh[0], bh[1]);
                mma16816(o[2*j2],   aph[kk], bl[0], bl[1]);
                mma16816(o[2*j2],   apl[kk], bh[0], bh[1]);
                mma16816(o[2*j2+1], aph[kk], bh[2], bh[3]);
                mma16816(o[2*j2+1], aph[kk], bl[2], bl[3]);
                mma16816(o[2*j2+1], apl[kk], bh[2], bh[3]);
            }
        }
        __syncthreads();   // done reading V before next K load
    }

    // ---- epilogue ----
    rs0 += __shfl_xor_sync(0xffffffffu, rs0, 1);
    rs0 += __shfl_xor_sync(0xffffffffu, rs0, 2);
    rs1 += __shfl_xor_sync(0xffffffffu, rs1, 1);
    rs1 += __shfl_xor_sync(0xffffffffu, rs1, 2);
    const float inv0 = 1.f / rs0;
    const float inv1 = 1.f / rs1;

    const int row0 = q0 + (w << 4) + (l >> 2);
    const int row1 = row0 + 8;
    const int colb = 2 * (l & 3);
    float* o0 = out + (size_t)(b * LL + row0) * HH + colb;
    float* o1 = out + (size_t)(b * LL + row1) * HH + colb;
    #pragma unroll
    for (int n = 0; n < 32; n++) {
        *(float2*)(o0 + 8 * n) = make_float2(o[n][0] * inv0, o[n][1] * inv0);
        *(float2*)(o1 + 8 * n) = make_float2(o[n][2] * inv1, o[n][3] * inv1);
    }
}

// ---------------------------------------------------------------------------
extern "C" void kernel_launch(void* const* d_in, const int* in_sizes, int n_in,
                              void* d_out, int out_size)
{
    const float* X    = (const float*)d_in[0];
    const float* Wq   = (const float*)d_in[1];
    const float* Wk   = (const float*)d_in[2];
    const float* Wv   = (const float*)d_in[3];
    const int*   lens = (const int*)d_in[4];
    float* out = (float*)d_out;

    cudaFuncSetAttribute(qkv_mma_kernel,
                         cudaFuncAttributeMaxDynamicSharedMemorySize, SMEM_TOTAL);
    qkv_mma_kernel<<<dim3(MTOT / 128), 256, SMEM_TOTAL>>>(X, Wq, Wk, Wv);

    cudaFuncSetAttribute(attn_kernel,
                         cudaFuncAttributeMaxDynamicSharedMemorySize, SMEM_TOTAL);
    attn_kernel<<<dim3(LL / 128, BB), 256, SMEM_TOTAL>>>(lens, out);
}

// round 6
// speedup vs baseline: 4.5284x; 1.2232x over previous
#include <cuda_runtime.h>
#include <cuda_bf16.h>
#include <cuda_fp16.h>
#include <math.h>

#define BB 8
#define LL 2048
#define HH 256
#define MTOT (BB*LL)

// Projected tensors: Q single fp16; K,V fp16 hi/lo splits. Row-major [b*L][H].
__device__ __align__(16) __half g_Q [MTOT*HH];
__device__ __align__(16) __half g_KH[MTOT*HH];
__device__ __align__(16) __half g_KL[MTOT*HH];
__device__ __align__(16) __half g_VH[MTOT*HH];
__device__ __align__(16) __half g_VL[MTOT*HH];

// ---------------- helpers ----------------
__device__ __forceinline__ unsigned smem_u32(const void* p) {
    unsigned a;
    asm("{ .reg .u64 t; cvta.to.shared.u64 t, %1; cvt.u32.u64 %0, t; }" : "=r"(a) : "l"(p));
    return a;
}
__device__ __forceinline__ unsigned packbf2(float e0, float e1) {
    unsigned r;  // low half = e0, high half = e1
    asm("cvt.rn.bf16x2.f32 %0, %1, %2;" : "=r"(r) : "f"(e1), "f"(e0));
    return r;
}
__device__ __forceinline__ unsigned packf2(float e0, float e1) {
    unsigned r;  // low half = e0, high half = e1
    asm("cvt.rn.f16x2.f32 %0, %1, %2;" : "=r"(r) : "f"(e1), "f"(e0));
    return r;
}
__device__ __forceinline__ void ldsm4(unsigned* r, unsigned addr) {
    asm volatile("ldmatrix.sync.aligned.m8n8.x4.shared.b16 {%0,%1,%2,%3}, [%4];"
                 : "=r"(r[0]), "=r"(r[1]), "=r"(r[2]), "=r"(r[3]) : "r"(addr));
}
__device__ __forceinline__ void ldsm4t(unsigned* r, unsigned addr) {
    asm volatile("ldmatrix.sync.aligned.m8n8.x4.trans.shared.b16 {%0,%1,%2,%3}, [%4];"
                 : "=r"(r[0]), "=r"(r[1]), "=r"(r[2]), "=r"(r[3]) : "r"(addr));
}
// bf16 mma (used by qkv projection)
__device__ __forceinline__ void mmab(float* c, const unsigned* a, unsigned b0, unsigned b1) {
    asm volatile(
        "mma.sync.aligned.m16n8k16.row.col.f32.bf16.bf16.f32 "
        "{%0,%1,%2,%3},{%4,%5,%6,%7},{%8,%9},{%0,%1,%2,%3};"
        : "+f"(c[0]), "+f"(c[1]), "+f"(c[2]), "+f"(c[3])
        : "r"(a[0]), "r"(a[1]), "r"(a[2]), "r"(a[3]), "r"(b0), "r"(b1));
}
// fp16 mma (attention)
__device__ __forceinline__ void mmah(float* c, const unsigned* a, unsigned b0, unsigned b1) {
    asm volatile(
        "mma.sync.aligned.m16n8k16.row.col.f32.f16.f16.f32 "
        "{%0,%1,%2,%3},{%4,%5,%6,%7},{%8,%9},{%0,%1,%2,%3};"
        : "+f"(c[0]), "+f"(c[1]), "+f"(c[2]), "+f"(c[3])
        : "r"(a[0]), "r"(a[1]), "r"(a[2]), "r"(a[3]), "r"(b0), "r"(b1));
}
__device__ __forceinline__ void cp16(unsigned dst, const void* src) {
    asm volatile("cp.async.cg.shared.global [%0], [%1], 16;" :: "r"(dst), "l"(src) : "memory");
}
__device__ __forceinline__ void cp_commit() { asm volatile("cp.async.commit_group;" ::: "memory"); }
__device__ __forceinline__ void cp_wait1()  { asm volatile("cp.async.wait_group 1;"  ::: "memory"); }

// smem tile layout: rows of 256 x 16-bit = 512B = 32 16B-chunks, XOR swizzle.
__device__ __forceinline__ unsigned tswz(int r, int c8) {
    return (unsigned)(r * 512 + ((c8 ^ (r & 7)) << 4));
}

// attention smem layout
#define SM_Q   0
#define SM_KH  65536
#define SM_KL  98304
#define SM_VH  131072
#define SM_VL  163840
#define SMEM_TOTAL 196608

// qkv smem layout
#define SM_XH 0
#define SM_XL 65536
#define SM_WH 131072
#define SM_WL 163840

// ---------------------------------------------------------------------------
// QKV projection on tensor cores (bf16 hi/lo x3 internally).
// Epilogue: Q -> single fp16; K,V -> fp16 hi/lo.
// ---------------------------------------------------------------------------
__global__ __launch_bounds__(256, 1) void qkv_mma_kernel(
    const float* __restrict__ X,
    const float* __restrict__ Wq,
    const float* __restrict__ Wk,
    const float* __restrict__ Wv)
{
    extern __shared__ char smc[];
    const unsigned sb = smem_u32(smc);
    const int tid = threadIdx.x;
    const int w   = tid >> 5;
    const int l   = tid & 31;
    const int m0  = blockIdx.x * 128;

    // ---- X tile -> bf16 hi/lo, swizzled ----
    #pragma unroll
    for (int it = 0; it < 16; it++) {
        int v = tid + it * 256;
        int r = v >> 5, c8 = v & 31;
        const float* src = X + (size_t)(m0 + r) * HH + c8 * 8;
        float4 a = *(const float4*)src;
        float4 c = *(const float4*)(src + 4);
        unsigned h0 = packbf2(a.x, a.y), h1 = packbf2(a.z, a.w);
        unsigned h2 = packbf2(c.x, c.y), h3 = packbf2(c.z, c.w);
        unsigned l0 = packbf2(a.x - __uint_as_float(h0 << 16), a.y - __uint_as_float(h0 & 0xFFFF0000u));
        unsigned l1 = packbf2(a.z - __uint_as_float(h1 << 16), a.w - __uint_as_float(h1 & 0xFFFF0000u));
        unsigned l2 = packbf2(c.x - __uint_as_float(h2 << 16), c.y - __uint_as_float(h2 & 0xFFFF0000u));
        unsigned l3 = packbf2(c.z - __uint_as_float(h3 << 16), c.w - __uint_as_float(h3 & 0xFFFF0000u));
        unsigned off = tswz(r, c8);
        *(uint4*)(smc + SM_XH + off) = make_uint4(h0, h1, h2, h3);
        *(uint4*)(smc + SM_XL + off) = make_uint4(l0, l1, l2, l3);
    }
    __syncthreads();

    const int qrow = (w << 4) + (l & 15);
    const int qx   = l >> 4;
    const int qsw  = qrow & 7;
    const unsigned xbH = SM_XH + (unsigned)qrow * 512;
    const unsigned xbL = SM_XL + (unsigned)qrow * 512;
    const int krl  = ((l & 16) >> 1) + (l & 7);
    const int kcp  = (l >> 3) & 1;

    #pragma unroll 1
    for (int z = 0; z < 3; z++) {
        const float* W = (z == 0) ? Wq : (z == 1) ? Wk : Wv;

        #pragma unroll 1
        for (int nt = 0; nt < 4; nt++) {
            // ---- W tile (64 out-rows x 256) -> bf16 hi/lo swizzled ----
            #pragma unroll
            for (int it = 0; it < 8; it++) {
                int v = tid + it * 256;
                int r = v >> 5, c8 = v & 31;
                const float* src = W + (size_t)(nt * 64 + r) * HH + c8 * 8;
                float4 a = *(const float4*)src;
                float4 c = *(const float4*)(src + 4);
                unsigned h0 = packbf2(a.x, a.y), h1 = packbf2(a.z, a.w);
                unsigned h2 = packbf2(c.x, c.y), h3 = packbf2(c.z, c.w);
                unsigned l0 = packbf2(a.x - __uint_as_float(h0 << 16), a.y - __uint_as_float(h0 & 0xFFFF0000u));
                unsigned l1 = packbf2(a.z - __uint_as_float(h1 << 16), a.w - __uint_as_float(h1 & 0xFFFF0000u));
                unsigned l2 = packbf2(c.x - __uint_as_float(h2 << 16), c.y - __uint_as_float(h2 & 0xFFFF0000u));
                unsigned l3 = packbf2(c.z - __uint_as_float(h3 << 16), c.w - __uint_as_float(h3 & 0xFFFF0000u));
                unsigned off = tswz(r, c8);
                *(uint4*)(smc + SM_WH + off) = make_uint4(h0, h1, h2, h3);
                *(uint4*)(smc + SM_WL + off) = make_uint4(l0, l1, l2, l3);
            }
            __syncthreads();

            float c[8][4];
            #pragma unroll
            for (int j = 0; j < 8; j++)
                #pragma unroll
                for (int e = 0; e < 4; e++) c[j][e] = 0.f;

            #pragma unroll 4
            for (int ks = 0; ks < 16; ks++) {
                unsigned ah[4], al[4];
                int ach = 2 * ks + qx;
                ldsm4(ah, sb + xbH + ((unsigned)((ach ^ qsw) << 4)));
                ldsm4(al, sb + xbL + ((unsigned)((ach ^ qsw) << 4)));
                #pragma unroll
                for (int j2 = 0; j2 < 4; j2++) {
                    unsigned boff = tswz((j2 << 4) + krl, 2 * ks + kcp);
                    unsigned bh[4], bl[4];
                    ldsm4(bh, sb + SM_WH + boff);
                    ldsm4(bl, sb + SM_WL + boff);
                    mmab(c[2*j2],   ah, bh[0], bh[1]);
                    mmab(c[2*j2],   ah, bl[0], bl[1]);
                    mmab(c[2*j2],   al, bh[0], bh[1]);
                    mmab(c[2*j2+1], ah, bh[2], bh[3]);
                    mmab(c[2*j2+1], ah, bl[2], bl[3]);
                    mmab(c[2*j2+1], al, bh[2], bh[3]);
                }
            }
            __syncthreads();

            // ---- epilogue ----
            const int row0 = m0 + (w << 4) + (l >> 2);
            const int col  = nt * 64 + 2 * (l & 3);
            if (z == 0) {
                #pragma unroll
                for (int j = 0; j < 8; j++) {
                    size_t base0 = (size_t)row0 * HH + col + j * 8;
                    size_t base1 = base0 + (size_t)8 * HH;
                    *(unsigned*)(g_Q + base0) = packf2(c[j][0], c[j][1]);
                    *(unsigned*)(g_Q + base1) = packf2(c[j][2], c[j][3]);
                }
            } else {
                __half* Yh = (z == 1) ? g_KH : g_VH;
                __half* Yl = (z == 1) ? g_KL : g_VL;
                #pragma unroll
                for (int j = 0; j < 8; j++) {
                    size_t base0 = (size_t)row0 * HH + col + j * 8;
                    size_t base1 = base0 + (size_t)8 * HH;
                    unsigned h01 = packf2(c[j][0], c[j][1]);
                    __half2 p01 = *(__half2*)&h01;
                    unsigned l01 = packf2(c[j][0] - __low2float(p01),
                                          c[j][1] - __high2float(p01));
                    unsigned h23 = packf2(c[j][2], c[j][3]);
                    __half2 p23 = *(__half2*)&h23;
                    unsigned l23 = packf2(c[j][2] - __low2float(p23),
                                          c[j][3] - __high2float(p23));
                    *(unsigned*)(Yh + base0) = h01;
                    *(unsigned*)(Yl + base0) = l01;
                    *(unsigned*)(Yh + base1) = h23;
                    *(unsigned*)(Yl + base1) = l23;
                }
            }
        }
    }
}

// ---------------------------------------------------------------------------
// fp16 flash attention, no-max softmax. Q/P single fp16; K/V hi-lo (2-pass).
// Separate K and V buffers; cp.async ring hides all load latency.
// CTA: 128 queries x batch; 8 warps x 16 q-rows; 64-key tiles; d=256.
// ---------------------------------------------------------------------------
__global__ __launch_bounds__(256, 1) void attn_kernel(
    const int* __restrict__ lens,
    float* __restrict__ out)
{
    extern __shared__ char smc[];
    const unsigned sb = smem_u32(smc);
    const int tid = threadIdx.x;
    const int w   = tid >> 5;
    const int l   = tid & 31;
    const int b   = blockIdx.y;
    const int q0  = blockIdx.x * 128;
    const int len = lens[b];
    const int nkt = (len + 63) >> 6;

    const __half* gK_h = g_KH + (size_t)b * LL * HH;
    const __half* gK_l = g_KL + (size_t)b * LL * HH;
    const __half* gV_h = g_VH + (size_t)b * LL * HH;
    const __half* gV_l = g_VL + (size_t)b * LL * HH;

    // ---- prologue: Q, K0, V0 as three cp.async groups ----
    {
        const __half* q = g_Q + (size_t)(b * LL + q0) * HH;
        #pragma unroll
        for (int it = 0; it < 16; it++) {
            int v = tid + it * 256;
            int r = v >> 5, c8 = v & 31;
            cp16(sb + SM_Q + tswz(r, c8), q + r * HH + c8 * 8);
        }
        cp_commit();
        #pragma unroll
        for (int it = 0; it < 8; it++) {
            int v = tid + it * 256;
            int r = v >> 5, c8 = v & 31;
            unsigned off = tswz(r, c8);
            cp16(sb + SM_KH + off, gK_h + r * HH + c8 * 8);
            cp16(sb + SM_KL + off, gK_l + r * HH + c8 * 8);
        }
        cp_commit();
        #pragma unroll
        for (int it = 0; it < 8; it++) {
            int v = tid + it * 256;
            int r = v >> 5, c8 = v & 31;
            unsigned off = tswz(r, c8);
            cp16(sb + SM_VH + off, gV_h + r * HH + c8 * 8);
            cp16(sb + SM_VL + off, gV_l + r * HH + c8 * 8);
        }
        cp_commit();
    }

    float o[32][4];
    #pragma unroll
    for (int n = 0; n < 32; n++)
        #pragma unroll
        for (int e = 0; e < 4; e++) o[n][e] = 0.f;
    float rs0 = 0.f, rs1 = 0.f;

    // lane constants
    const int qrow = (w << 4) + (l & 15);
    const int qx   = l >> 4;
    const int qsw  = qrow & 7;
    const unsigned qb = SM_Q + (unsigned)qrow * 512;
    const int krl  = ((l & 16) >> 1) + (l & 7);
    const int kcp  = (l >> 3) & 1;
    const int vrl  = (((l >> 3) & 1) << 3) + (l & 7);
    const int vco  = l >> 4;

    const float SC = 0.0625f;  // 1/sqrt(256)

    for (int kt = 0; kt < nkt; kt++) {
        const int k0 = kt << 6;

        cp_wait1();          // K(kt) ready (V(kt) may still be in flight)
        __syncthreads();

        // ---- S = Q (Kh + Kl)^T : 2 passes ----
        float s[8][4];
        #pragma unroll
        for (int j = 0; j < 8; j++)
            #pragma unroll
            for (int e = 0; e < 4; e++) s[j][e] = 0.f;

        #pragma unroll 4
        for (int ks = 0; ks < 16; ks++) {
            unsigned ah[4];
            int ach = 2 * ks + qx;
            ldsm4(ah, sb + qb + ((unsigned)((ach ^ qsw) << 4)));
            #pragma unroll
            for (int j2 = 0; j2 < 4; j2++) {
                unsigned boff = tswz((j2 << 4) + krl, 2 * ks + kcp);
                unsigned bh[4], bl[4];
                ldsm4(bh, sb + SM_KH + boff);
                ldsm4(bl, sb + SM_KL + boff);
                mmah(s[2*j2],   ah, bh[0], bh[1]);
                mmah(s[2*j2],   ah, bl[0], bl[1]);
                mmah(s[2*j2+1], ah, bh[2], bh[3]);
                mmah(s[2*j2+1], ah, bl[2], bl[3]);
            }
        }

        // ---- softmax (registers; P single fp16) ----
        unsigned aph[4][4];
        if (k0 + 64 <= len) {
            #pragma unroll
            for (int kk = 0; kk < 4; kk++) {
                #pragma unroll
                for (int h = 0; h < 2; h++) {
                    int j = 2 * kk + h;
                    float p0 = __expf(s[j][0] * SC);
                    float p1 = __expf(s[j][1] * SC);
                    float p2 = __expf(s[j][2] * SC);
                    float p3 = __expf(s[j][3] * SC);
                    rs0 += p0 + p1;
                    rs1 += p2 + p3;
                    aph[kk][2*h+0] = packf2(p0, p1);
                    aph[kk][2*h+1] = packf2(p2, p3);
                }
            }
        } else {
            #pragma unroll
            for (int kk = 0; kk < 4; kk++) {
                #pragma unroll
                for (int h = 0; h < 2; h++) {
                    int j = 2 * kk + h;
                    int col = k0 + 8 * j + 2 * (l & 3);
                    float p0 = (col     < len) ? __expf(s[j][0] * SC) : 0.f;
                    float p1 = (col + 1 < len) ? __expf(s[j][1] * SC) : 0.f;
                    float p2 = (col     < len) ? __expf(s[j][2] * SC) : 0.f;
                    float p3 = (col + 1 < len) ? __expf(s[j][3] * SC) : 0.f;
                    rs0 += p0 + p1;
                    rs1 += p2 + p3;
                    aph[kk][2*h+0] = packf2(p0, p1);
                    aph[kk][2*h+1] = packf2(p2, p3);
                }
            }
        }
        __syncthreads();     // all warps done reading K buffer

        // ---- prefetch K(kt+1) into K buffer ----
        if (kt + 1 < nkt) {
            const __half* kh = gK_h + (size_t)(k0 + 64) * HH;
            const __half* kl = gK_l + (size_t)(k0 + 64) * HH;
            #pragma unroll
            for (int it = 0; it < 8; it++) {
                int v = tid + it * 256;
                int r = v >> 5, c8 = v & 31;
                unsigned off = tswz(r, c8);
                cp16(sb + SM_KH + off, kh + r * HH + c8 * 8);
                cp16(sb + SM_KL + off, kl + r * HH + c8 * 8);
            }
        }
        cp_commit();

        cp_wait1();          // V(kt) ready (K(kt+1) may be in flight)
        __syncthreads();

        // ---- O += P (Vh + Vl) : 2 passes ----
        #pragma unroll
        for (int kk = 0; kk < 4; kk++) {
            #pragma unroll
            for (int j2 = 0; j2 < 16; j2++) {
                unsigned voff = tswz((kk << 4) + vrl, 2 * j2 + vco);
                unsigned vh[4], vl[4];
                ldsm4t(vh, sb + SM_VH + voff);
                ldsm4t(vl, sb + SM_VL + voff);
                mmah(o[2*j2],   aph[kk], vh[0], vh[1]);
                mmah(o[2*j2],   aph[kk], vl[0], vl[1]);
                mmah(o[2*j2+1], aph[kk], vh[2], vh[3]);
                mmah(o[2*j2+1], aph[kk], vl[2], vl[3]);
            }
        }
        __syncthreads();     // all warps done reading V buffer

        // ---- prefetch V(kt+1) into V buffer ----
        if (kt + 1 < nkt) {
            const __half* vh = gV_h + (size_t)(k0 + 64) * HH;
            const __half* vl = gV_l + (size_t)(k0 + 64) * HH;
            #pragma unroll
            for (int it = 0; it < 8; it++) {
                int v = tid + it * 256;
                int r = v >> 5, c8 = v & 31;
                unsigned off = tswz(r, c8);
                cp16(sb + SM_VH + off, vh + r * HH + c8 * 8);
                cp16(sb + SM_VL + off, vl + r * HH + c8 * 8);
            }
        }
        cp_commit();
    }

    // ---- epilogue ----
    rs0 += __shfl_xor_sync(0xffffffffu, rs0, 1);
    rs0 += __shfl_xor_sync(0xffffffffu, rs0, 2);
    rs1 += __shfl_xor_sync(0xffffffffu, rs1, 1);
    rs1 += __shfl_xor_sync(0xffffffffu, rs1, 2);
    const float inv0 = 1.f / rs0;
    const float inv1 = 1.f / rs1;

    const int row0 = q0 + (w << 4) + (l >> 2);
    const int row1 = row0 + 8;
    const int colb = 2 * (l & 3);
    float* o0 = out + (size_t)(b * LL + row0) * HH + colb;
    float* o1 = out + (size_t)(b * LL + row1) * HH + colb;
    #pragma unroll
    for (int n = 0; n < 32; n++) {
        *(float2*)(o0 + 8 * n) = make_float2(o[n][0] * inv0, o[n][1] * inv0);
        *(float2*)(o1 + 8 * n) = make_float2(o[n][2] * inv1, o[n][3] * inv1);
    }
}

// ---------------------------------------------------------------------------
extern "C" void kernel_launch(void* const* d_in, const int* in_sizes, int n_in,
                              void* d_out, int out_size)
{
    const float* X    = (const float*)d_in[0];
    const float* Wq   = (const float*)d_in[1];
    const float* Wk   = (const float*)d_in[2];
    const float* Wv   = (const float*)d_in[3];
    const int*   lens = (const int*)d_in[4];
    float* out = (float*)d_out;

    cudaFuncSetAttribute(qkv_mma_kernel,
                         cudaFuncAttributeMaxDynamicSharedMemorySize, SMEM_TOTAL);
    qkv_mma_kernel<<<dim3(MTOT / 128), 256, SMEM_TOTAL>>>(X, Wq, Wk, Wv);

    cudaFuncSetAttribute(attn_kernel,
                         cudaFuncAttributeMaxDynamicSharedMemorySize, SMEM_TOTAL);
    attn_kernel<<<dim3(LL / 128, BB), 256, SMEM_TOTAL>>>(lens, out);
}

// round 7
// speedup vs baseline: 4.7408x; 1.0469x over previous
#include <cuda_runtime.h>
#include <cuda_bf16.h>
#include <cuda_fp16.h>
#include <math.h>

#define BB 8
#define LL 2048
#define HH 256
#define MTOT (BB*LL)

// Projected tensors: single fp16. Row-major [b*L][H].
__device__ __align__(16) __half g_Q[MTOT*HH];
__device__ __align__(16) __half g_K[MTOT*HH];
__device__ __align__(16) __half g_V[MTOT*HH];

// ---------------- helpers ----------------
__device__ __forceinline__ unsigned smem_u32(const void* p) {
    unsigned a;
    asm("{ .reg .u64 t; cvta.to.shared.u64 t, %1; cvt.u32.u64 %0, t; }" : "=r"(a) : "l"(p));
    return a;
}
__device__ __forceinline__ unsigned packbf2(float e0, float e1) {
    unsigned r;  // low half = e0, high half = e1
    asm("cvt.rn.bf16x2.f32 %0, %1, %2;" : "=r"(r) : "f"(e1), "f"(e0));
    return r;
}
__device__ __forceinline__ unsigned packf2(float e0, float e1) {
    unsigned r;  // low half = e0, high half = e1
    asm("cvt.rn.f16x2.f32 %0, %1, %2;" : "=r"(r) : "f"(e1), "f"(e0));
    return r;
}
__device__ __forceinline__ void ldsm4(unsigned* r, unsigned addr) {
    asm volatile("ldmatrix.sync.aligned.m8n8.x4.shared.b16 {%0,%1,%2,%3}, [%4];"
                 : "=r"(r[0]), "=r"(r[1]), "=r"(r[2]), "=r"(r[3]) : "r"(addr));
}
__device__ __forceinline__ void ldsm4t(unsigned* r, unsigned addr) {
    asm volatile("ldmatrix.sync.aligned.m8n8.x4.trans.shared.b16 {%0,%1,%2,%3}, [%4];"
                 : "=r"(r[0]), "=r"(r[1]), "=r"(r[2]), "=r"(r[3]) : "r"(addr));
}
// bf16 mma (qkv projection, hi/lo x3)
__device__ __forceinline__ void mmab(float* c, const unsigned* a, unsigned b0, unsigned b1) {
    asm volatile(
        "mma.sync.aligned.m16n8k16.row.col.f32.bf16.bf16.f32 "
        "{%0,%1,%2,%3},{%4,%5,%6,%7},{%8,%9},{%0,%1,%2,%3};"
        : "+f"(c[0]), "+f"(c[1]), "+f"(c[2]), "+f"(c[3])
        : "r"(a[0]), "r"(a[1]), "r"(a[2]), "r"(a[3]), "r"(b0), "r"(b1));
}
// fp16 mma (attention)
__device__ __forceinline__ void mmah(float* c, const unsigned* a, unsigned b0, unsigned b1) {
    asm volatile(
        "mma.sync.aligned.m16n8k16.row.col.f32.f16.f16.f32 "
        "{%0,%1,%2,%3},{%4,%5,%6,%7},{%8,%9},{%0,%1,%2,%3};"
        : "+f"(c[0]), "+f"(c[1]), "+f"(c[2]), "+f"(c[3])
        : "r"(a[0]), "r"(a[1]), "r"(a[2]), "r"(a[3]), "r"(b0), "r"(b1));
}
__device__ __forceinline__ void cp16(unsigned dst, const void* src) {
    asm volatile("cp.async.cg.shared.global [%0], [%1], 16;" :: "r"(dst), "l"(src) : "memory");
}
__device__ __forceinline__ void cp_commit() { asm volatile("cp.async.commit_group;" ::: "memory"); }
__device__ __forceinline__ void cp_wait1()  { asm volatile("cp.async.wait_group 1;"  ::: "memory"); }

// smem tile layout: rows of 256 x 16-bit = 512B = 32 16B-chunks, XOR swizzle.
__device__ __forceinline__ unsigned tswz(int r, int c8) {
    return (unsigned)(r * 512 + ((c8 ^ (r & 7)) << 4));
}

// attention smem layout: Q 64KB; K double-buffer 2x32KB; V double-buffer 2x32KB
#define SM_Q   0
#define SM_K0  65536
#define SM_K1  98304
#define SM_V0  131072
#define SM_V1  163840
#define SMEM_TOTAL 196608

// qkv smem layout
#define SM_XH 0
#define SM_XL 65536
#define SM_WH 131072
#define SM_WL 163840

// ---------------------------------------------------------------------------
// QKV projection on tensor cores (bf16 hi/lo x3 internally), fp16 outputs.
// ---------------------------------------------------------------------------
__global__ __launch_bounds__(256, 1) void qkv_mma_kernel(
    const float* __restrict__ X,
    const float* __restrict__ Wq,
    const float* __restrict__ Wk,
    const float* __restrict__ Wv)
{
    extern __shared__ char smc[];
    const unsigned sb = smem_u32(smc);
    const int tid = threadIdx.x;
    const int w   = tid >> 5;
    const int l   = tid & 31;
    const int m0  = blockIdx.x * 128;

    // ---- X tile -> bf16 hi/lo, swizzled ----
    #pragma unroll
    for (int it = 0; it < 16; it++) {
        int v = tid + it * 256;
        int r = v >> 5, c8 = v & 31;
        const float* src = X + (size_t)(m0 + r) * HH + c8 * 8;
        float4 a = *(const float4*)src;
        float4 c = *(const float4*)(src + 4);
        unsigned h0 = packbf2(a.x, a.y), h1 = packbf2(a.z, a.w);
        unsigned h2 = packbf2(c.x, c.y), h3 = packbf2(c.z, c.w);
        unsigned l0 = packbf2(a.x - __uint_as_float(h0 << 16), a.y - __uint_as_float(h0 & 0xFFFF0000u));
        unsigned l1 = packbf2(a.z - __uint_as_float(h1 << 16), a.w - __uint_as_float(h1 & 0xFFFF0000u));
        unsigned l2 = packbf2(c.x - __uint_as_float(h2 << 16), c.y - __uint_as_float(h2 & 0xFFFF0000u));
        unsigned l3 = packbf2(c.z - __uint_as_float(h3 << 16), c.w - __uint_as_float(h3 & 0xFFFF0000u));
        unsigned off = tswz(r, c8);
        *(uint4*)(smc + SM_XH + off) = make_uint4(h0, h1, h2, h3);
        *(uint4*)(smc + SM_XL + off) = make_uint4(l0, l1, l2, l3);
    }
    __syncthreads();

    const int qrow = (w << 4) + (l & 15);
    const int qx   = l >> 4;
    const int qsw  = qrow & 7;
    const unsigned xbH = SM_XH + (unsigned)qrow * 512;
    const unsigned xbL = SM_XL + (unsigned)qrow * 512;
    const int krl  = ((l & 16) >> 1) + (l & 7);
    const int kcp  = (l >> 3) & 1;

    #pragma unroll 1
    for (int z = 0; z < 3; z++) {
        const float* W = (z == 0) ? Wq : (z == 1) ? Wk : Wv;
        __half* Y = (z == 0) ? g_Q : (z == 1) ? g_K : g_V;

        #pragma unroll 1
        for (int nt = 0; nt < 4; nt++) {
            // ---- W tile (64 out-rows x 256) -> bf16 hi/lo swizzled ----
            #pragma unroll
            for (int it = 0; it < 8; it++) {
                int v = tid + it * 256;
                int r = v >> 5, c8 = v & 31;
                const float* src = W + (size_t)(nt * 64 + r) * HH + c8 * 8;
                float4 a = *(const float4*)src;
                float4 c = *(const float4*)(src + 4);
                unsigned h0 = packbf2(a.x, a.y), h1 = packbf2(a.z, a.w);
                unsigned h2 = packbf2(c.x, c.y), h3 = packbf2(c.z, c.w);
                unsigned l0 = packbf2(a.x - __uint_as_float(h0 << 16), a.y - __uint_as_float(h0 & 0xFFFF0000u));
                unsigned l1 = packbf2(a.z - __uint_as_float(h1 << 16), a.w - __uint_as_float(h1 & 0xFFFF0000u));
                unsigned l2 = packbf2(c.x - __uint_as_float(h2 << 16), c.y - __uint_as_float(h2 & 0xFFFF0000u));
                unsigned l3 = packbf2(c.z - __uint_as_float(h3 << 16), c.w - __uint_as_float(h3 & 0xFFFF0000u));
                unsigned off = tswz(r, c8);
                *(uint4*)(smc + SM_WH + off) = make_uint4(h0, h1, h2, h3);
                *(uint4*)(smc + SM_WL + off) = make_uint4(l0, l1, l2, l3);
            }
            __syncthreads();

            float c[8][4];
            #pragma unroll
            for (int j = 0; j < 8; j++)
                #pragma unroll
                for (int e = 0; e < 4; e++) c[j][e] = 0.f;

            #pragma unroll 4
            for (int ks = 0; ks < 16; ks++) {
                unsigned ah[4], al[4];
                int ach = 2 * ks + qx;
                ldsm4(ah, sb + xbH + ((unsigned)((ach ^ qsw) << 4)));
                ldsm4(al, sb + xbL + ((unsigned)((ach ^ qsw) << 4)));
                #pragma unroll
                for (int j2 = 0; j2 < 4; j2++) {
                    unsigned boff = tswz((j2 << 4) + krl, 2 * ks + kcp);
                    unsigned bh[4], bl[4];
                    ldsm4(bh, sb + SM_WH + boff);
                    ldsm4(bl, sb + SM_WL + boff);
                    mmab(c[2*j2],   ah, bh[0], bh[1]);
                    mmab(c[2*j2],   ah, bl[0], bl[1]);
                    mmab(c[2*j2],   al, bh[0], bh[1]);
                    mmab(c[2*j2+1], ah, bh[2], bh[3]);
                    mmab(c[2*j2+1], ah, bl[2], bl[3]);
                    mmab(c[2*j2+1], al, bh[2], bh[3]);
                }
            }
            __syncthreads();

            // ---- epilogue: single fp16 ----
            const int row0 = m0 + (w << 4) + (l >> 2);
            const int col  = nt * 64 + 2 * (l & 3);
            #pragma unroll
            for (int j = 0; j < 8; j++) {
                size_t base0 = (size_t)row0 * HH + col + j * 8;
                size_t base1 = base0 + (size_t)8 * HH;
                *(unsigned*)(Y + base0) = packf2(c[j][0], c[j][1]);
                *(unsigned*)(Y + base1) = packf2(c[j][2], c[j][3]);
            }
        }
    }
}

// ---------------------------------------------------------------------------
// fp16 flash attention, no-max softmax, single-precision fp16 operands.
// Double-buffered K and V; one commit/wait + two barriers per key tile.
// CTA: 128 queries x batch; 8 warps x 16 q-rows; 64-key tiles; d=256.
// ---------------------------------------------------------------------------
__global__ __launch_bounds__(256, 1) void attn_kernel(
    const int* __restrict__ lens,
    float* __restrict__ out)
{
    extern __shared__ char smc[];
    const unsigned sb = smem_u32(smc);
    const int tid = threadIdx.x;
    const int w   = tid >> 5;
    const int l   = tid & 31;
    const int b   = blockIdx.y;
    const int q0  = blockIdx.x * 128;
    const int len = lens[b];
    const int nkt = (len + 63) >> 6;

    const __half* gK = g_K + (size_t)b * LL * HH;
    const __half* gV = g_V + (size_t)b * LL * HH;

    // ---- prologue: group0 = {Q, K0, V0} ----
    {
        const __half* q = g_Q + (size_t)(b * LL + q0) * HH;
        #pragma unroll
        for (int it = 0; it < 16; it++) {
            int v = tid + it * 256;
            int r = v >> 5, c8 = v & 31;
            cp16(sb + SM_Q + tswz(r, c8), q + r * HH + c8 * 8);
        }
        #pragma unroll
        for (int it = 0; it < 4; it++) {
            int v = tid + it * 256;
            int r = v >> 4, c8 = v & 15;
            unsigned off = tswz(r, c8 + ((r & 1) << 4));  // dummy-free: rows 0..63, c8 0..31
            (void)off;
        }
        #pragma unroll
        for (int it = 0; it < 8; it++) {
            int v = tid + it * 256;
            int r = v >> 5, c8 = v & 31;
            unsigned off = tswz(r, c8);
            cp16(sb + SM_K0 + off, gK + r * HH + c8 * 8);
            cp16(sb + SM_V0 + off, gV + r * HH + c8 * 8);
        }
        cp_commit();
    }

    float o[32][4];
    #pragma unroll
    for (int n = 0; n < 32; n++)
        #pragma unroll
        for (int e = 0; e < 4; e++) o[n][e] = 0.f;
    float rs0 = 0.f, rs1 = 0.f;

    // lane constants
    const int qrow = (w << 4) + (l & 15);
    const int qx   = l >> 4;
    const int qsw  = qrow & 7;
    const unsigned qb = SM_Q + (unsigned)qrow * 512;
    const int krl  = ((l & 16) >> 1) + (l & 7);
    const int kcp  = (l >> 3) & 1;
    const int vrl  = (((l >> 3) & 1) << 3) + (l & 7);
    const int vco  = l >> 4;

    const float SC = 0.0625f;  // 1/sqrt(256)

    for (int kt = 0; kt < nkt; kt++) {
        const int k0 = kt << 6;
        const int cur = kt & 1;
        const unsigned kbuf = cur ? SM_K1 : SM_K0;
        const unsigned vbuf = cur ? SM_V1 : SM_V0;

        // ---- prefetch K(t+1), V(t+1) into the other buffers ----
        if (kt + 1 < nkt) {
            const unsigned kn = cur ? SM_K0 : SM_K1;
            const unsigned vn = cur ? SM_V0 : SM_V1;
            const __half* kh = gK + (size_t)(k0 + 64) * HH;
            const __half* vh = gV + (size_t)(k0 + 64) * HH;
            #pragma unroll
            for (int it = 0; it < 8; it++) {
                int v = tid + it * 256;
                int r = v >> 5, c8 = v & 31;
                unsigned off = tswz(r, c8);
                cp16(sb + kn + off, kh + r * HH + c8 * 8);
                cp16(sb + vn + off, vh + r * HH + c8 * 8);
            }
        }
        cp_commit();
        cp_wait1();          // group(t) complete; group(t+1) may be in flight
        __syncthreads();

        // ---- S = Q K^T ----
        float s[8][4];
        #pragma unroll
        for (int j = 0; j < 8; j++)
            #pragma unroll
            for (int e = 0; e < 4; e++) s[j][e] = 0.f;

        #pragma unroll 4
        for (int ks = 0; ks < 16; ks++) {
            unsigned ah[4];
            int ach = 2 * ks + qx;
            ldsm4(ah, sb + qb + ((unsigned)((ach ^ qsw) << 4)));
            #pragma unroll
            for (int j2 = 0; j2 < 4; j2++) {
                unsigned bh[4];
                ldsm4(bh, sb + kbuf + tswz((j2 << 4) + krl, 2 * ks + kcp));
                mmah(s[2*j2],   ah, bh[0], bh[1]);
                mmah(s[2*j2+1], ah, bh[2], bh[3]);
            }
        }

        // ---- softmax (registers; P single fp16) ----
        unsigned aph[4][4];
        if (k0 + 64 <= len) {
            #pragma unroll
            for (int kk = 0; kk < 4; kk++) {
                #pragma unroll
                for (int h = 0; h < 2; h++) {
                    int j = 2 * kk + h;
                    float p0 = __expf(s[j][0] * SC);
                    float p1 = __expf(s[j][1] * SC);
                    float p2 = __expf(s[j][2] * SC);
                    float p3 = __expf(s[j][3] * SC);
                    rs0 += p0 + p1;
                    rs1 += p2 + p3;
                    aph[kk][2*h+0] = packf2(p0, p1);
                    aph[kk][2*h+1] = packf2(p2, p3);
                }
            }
        } else {
            #pragma unroll
            for (int kk = 0; kk < 4; kk++) {
                #pragma unroll
                for (int h = 0; h < 2; h++) {
                    int j = 2 * kk + h;
                    int col = k0 + 8 * j + 2 * (l & 3);
                    float p0 = (col     < len) ? __expf(s[j][0] * SC) : 0.f;
                    float p1 = (col + 1 < len) ? __expf(s[j][1] * SC) : 0.f;
                    float p2 = (col     < len) ? __expf(s[j][2] * SC) : 0.f;
                    float p3 = (col + 1 < len) ? __expf(s[j][3] * SC) : 0.f;
                    rs0 += p0 + p1;
                    rs1 += p2 + p3;
                    aph[kk][2*h+0] = packf2(p0, p1);
                    aph[kk][2*h+1] = packf2(p2, p3);
                }
            }
        }

        // ---- O += P V ----
        #pragma unroll
        for (int kk = 0; kk < 4; kk++) {
            #pragma unroll
            for (int j2 = 0; j2 < 16; j2++) {
                unsigned vh[4];
                ldsm4t(vh, sb + vbuf + tswz((kk << 4) + vrl, 2 * j2 + vco));
                mmah(o[2*j2],   aph[kk], vh[0], vh[1]);
                mmah(o[2*j2+1], aph[kk], vh[2], vh[3]);
            }
        }
        __syncthreads();     // all warps done with buf(cur) before it is refilled
    }

    // ---- epilogue ----
    rs0 += __shfl_xor_sync(0xffffffffu, rs0, 1);
    rs0 += __shfl_xor_sync(0xffffffffu, rs0, 2);
    rs1 += __shfl_xor_sync(0xffffffffu, rs1, 1);
    rs1 += __shfl_xor_sync(0xffffffffu, rs1, 2);
    const float inv0 = 1.f / rs0;
    const float inv1 = 1.f / rs1;

    const int row0 = q0 + (w << 4) + (l >> 2);
    const int row1 = row0 + 8;
    const int colb = 2 * (l & 3);
    float* o0 = out + (size_t)(b * LL + row0) * HH + colb;
    float* o1 = out + (size_t)(b * LL + row1) * HH + colb;
    #pragma unroll
    for (int n = 0; n < 32; n++) {
        *(float2*)(o0 + 8 * n) = make_float2(o[n][0] * inv0, o[n][1] * inv0);
        *(float2*)(o1 + 8 * n) = make_float2(o[n][2] * inv1, o[n][3] * inv1);
    }
}

// ---------------------------------------------------------------------------
extern "C" void kernel_launch(void* const* d_in, const int* in_sizes, int n_in,
                              void* d_out, int out_size)
{
    const float* X    = (const float*)d_in[0];
    const float* Wq   = (const float*)d_in[1];
    const float* Wk   = (const float*)d_in[2];
    const float* Wv   = (const float*)d_in[3];
    const int*   lens = (const int*)d_in[4];
    float* out = (float*)d_out;

    cudaFuncSetAttribute(qkv_mma_kernel,
                         cudaFuncAttributeMaxDynamicSharedMemorySize, SMEM_TOTAL);
    qkv_mma_kernel<<<dim3(MTOT / 128), 256, SMEM_TOTAL>>>(X, Wq, Wk, Wv);

    cudaFuncSetAttribute(attn_kernel,
                         cudaFuncAttributeMaxDynamicSharedMemorySize, SMEM_TOTAL);
    attn_kernel<<<dim3(LL / 128, BB), 256, SMEM_TOTAL>>>(lens, out);
}

// round 11
// speedup vs baseline: 7.8219x; 1.6499x over previous
#include <cuda_runtime.h>
#include <cuda_bf16.h>
#include <cuda_fp16.h>
#include <math.h>

#define BB 8
#define LL 2048
#define HH 256
#define MTOT (BB*LL)

// Projected tensors: single fp16. Row-major [b*L][H].
__device__ __align__(16) __half g_Q[MTOT*HH];
__device__ __align__(16) __half g_K[MTOT*HH];
__device__ __align__(16) __half g_V[MTOT*HH];

// ---------------- helpers ----------------
__device__ __forceinline__ unsigned smem_u32(const void* p) {
    unsigned a;
    asm("{ .reg .u64 t; cvta.to.shared.u64 t, %1; cvt.u32.u64 %0, t; }" : "=r"(a) : "l"(p));
    return a;
}
__device__ __forceinline__ unsigned packf2(float e0, float e1) {
    unsigned r;  // low half = e0, high half = e1
    asm("cvt.rn.f16x2.f32 %0, %1, %2;" : "=r"(r) : "f"(e1), "f"(e0));
    return r;
}
__device__ __forceinline__ float ex2(float x) {
    float r;
    asm("ex2.approx.f32 %0, %1;" : "=f"(r) : "f"(x));
    return r;
}
__device__ __forceinline__ void ldsm4(unsigned* r, unsigned addr) {
    asm volatile("ldmatrix.sync.aligned.m8n8.x4.shared.b16 {%0,%1,%2,%3}, [%4];"
                 : "=r"(r[0]), "=r"(r[1]), "=r"(r[2]), "=r"(r[3]) : "r"(addr));
}
__device__ __forceinline__ void ldsm4t(unsigned* r, unsigned addr) {
    asm volatile("ldmatrix.sync.aligned.m8n8.x4.trans.shared.b16 {%0,%1,%2,%3}, [%4];"
                 : "=r"(r[0]), "=r"(r[1]), "=r"(r[2]), "=r"(r[3]) : "r"(addr));
}
__device__ __forceinline__ void mmah(float* c, const unsigned* a, unsigned b0, unsigned b1) {
    asm volatile(
        "mma.sync.aligned.m16n8k16.row.col.f32.f16.f16.f32 "
        "{%0,%1,%2,%3},{%4,%5,%6,%7},{%8,%9},{%0,%1,%2,%3};"
        : "+f"(c[0]), "+f"(c[1]), "+f"(c[2]), "+f"(c[3])
        : "r"(a[0]), "r"(a[1]), "r"(a[2]), "r"(a[3]), "r"(b0), "r"(b1));
}
__device__ __forceinline__ void cp16(unsigned dst, const void* src) {
    asm volatile("cp.async.cg.shared.global [%0], [%1], 16;" :: "r"(dst), "l"(src) : "memory");
}
__device__ __forceinline__ void cp_commit() { asm volatile("cp.async.commit_group;" ::: "memory"); }
__device__ __forceinline__ void cp_wait0()  { asm volatile("cp.async.wait_group 0;"  ::: "memory"); }
__device__ __forceinline__ void cp_wait1()  { asm volatile("cp.async.wait_group 1;"  ::: "memory"); }

// smem tile layout: rows of 256 x 16-bit = 512B = 32 16B-chunks, XOR swizzle.
__device__ __forceinline__ unsigned tswz(int r, int c8) {
    return (unsigned)(r * 512 + ((c8 ^ (r & 7)) << 4));
}

// attention smem layout: Q 64KB; K double-buffer 2x32KB; V double-buffer 2x32KB
#define SM_Q   0
#define SM_K0  65536
#define SM_K1  98304
#define SM_V0  131072
#define SM_V1  163840
#define SMEM_TOTAL 196608

// qkv smem layout: X fp16 64KB; W hi/lo 2x32KB; W fp32 staging 64KB
#define QK_X   0
#define QK_WH  65536
#define QK_WL  98304
#define QK_WS  131072

// ---------------------------------------------------------------------------
// QKV projection on tensor cores. X single fp16; W fp16 hi/lo (2 passes).
// W tiles prefetched fp32 via cp.async into smem staging (latency hidden).
// ---------------------------------------------------------------------------
__global__ __launch_bounds__(256, 1) void qkv_mma_kernel(
    const float* __restrict__ X,
    const float* __restrict__ Wq,
    const float* __restrict__ Wk,
    const float* __restrict__ Wv)
{
    extern __shared__ char smc[];
    const unsigned sb = smem_u32(smc);
    const int tid = threadIdx.x;
    const int w   = tid >> 5;
    const int l   = tid & 31;
    const int m0  = blockIdx.x * 128;

    const float* Ws[3] = { Wq, Wk, Wv };

    // ---- issue cp.async for W tile 0 fp32 into staging ----
    #pragma unroll
    for (int it = 0; it < 16; it++) {
        int v = tid + it * 256;
        int r = v >> 6, c16 = v & 63;                 // 64 rows x 64 16B-chunks
        cp16(sb + QK_WS + r * 1024 + c16 * 16, Wq + (size_t)r * HH + c16 * 4);
    }
    cp_commit();

    // ---- X tile -> single fp16, swizzled (overlaps the W cp.async) ----
    #pragma unroll
    for (int it = 0; it < 16; it++) {
        int v = tid + it * 256;
        int r = v >> 5, c8 = v & 31;
        const float* src = X + (size_t)(m0 + r) * HH + c8 * 8;
        float4 a = *(const float4*)src;
        float4 c = *(const float4*)(src + 4);
        *(uint4*)(smc + QK_X + tswz(r, c8)) =
            make_uint4(packf2(a.x, a.y), packf2(a.z, a.w),
                       packf2(c.x, c.y), packf2(c.z, c.w));
    }

    const int qrow = (w << 4) + (l & 15);
    const int qx   = l >> 4;
    const int qsw  = qrow & 7;
    const unsigned xb = QK_X + (unsigned)qrow * 512;
    const int krl  = ((l & 16) >> 1) + (l & 7);
    const int kcp  = (l >> 3) & 1;

    #pragma unroll 1
    for (int t = 0; t < 12; t++) {
        const int z  = t >> 2;
        const int nt = t & 3;

        cp_wait0();
        __syncthreads();     // W(t) staging ready; previous MMA done with WH/WL

        // ---- convert staging fp32 -> WH/WL fp16 hi/lo (swizzled) ----
        #pragma unroll
        for (int it = 0; it < 8; it++) {
            int v = tid + it * 256;
            int r = v >> 5, c8 = v & 31;
            const float* src = (const float*)(smc + QK_WS + r * 1024 + c8 * 32);
            float4 a = *(const float4*)src;
            float4 c = *(const float4*)(src + 4);
            unsigned h0 = packf2(a.x, a.y), h1 = packf2(a.z, a.w);
            unsigned h2 = packf2(c.x, c.y), h3 = packf2(c.z, c.w);
            __half2 p0 = *(__half2*)&h0, p1 = *(__half2*)&h1;
            __half2 p2 = *(__half2*)&h2, p3 = *(__half2*)&h3;
            unsigned l0 = packf2(a.x - __low2float(p0), a.y - __high2float(p0));
            unsigned l1 = packf2(a.z - __low2float(p1), a.w - __high2float(p1));
            unsigned l2 = packf2(c.x - __low2float(p2), c.y - __high2float(p2));
            unsigned l3 = packf2(c.z - __low2float(p3), c.w - __high2float(p3));
            unsigned off = tswz(r, c8);
            *(uint4*)(smc + QK_WH + off) = make_uint4(h0, h1, h2, h3);
            *(uint4*)(smc + QK_WL + off) = make_uint4(l0, l1, l2, l3);
        }
        __syncthreads();     // WH/WL ready; staging free

        // ---- prefetch W(t+1) fp32 into staging ----
        if (t + 1 < 12) {
            const float* Wn = Ws[(t + 1) >> 2] + (size_t)(((t + 1) & 3) * 64) * HH;
            #pragma unroll
            for (int it = 0; it < 16; it++) {
                int v = tid + it * 256;
                int r = v >> 6, c16 = v & 63;
                cp16(sb + QK_WS + r * 1024 + c16 * 16, Wn + (size_t)r * HH + c16 * 4);
            }
        }
        cp_commit();

        // ---- MMA: Y = Xh * (Wh + Wl)^T ----
        float c[8][4];
        #pragma unroll
        for (int j = 0; j < 8; j++)
            #pragma unroll
            for (int e = 0; e < 4; e++) c[j][e] = 0.f;

        #pragma unroll 8
        for (int ks = 0; ks < 16; ks++) {
            unsigned ax[4];
            int ach = 2 * ks + qx;
            ldsm4(ax, sb + xb + ((unsigned)((ach ^ qsw) << 4)));
            #pragma unroll
            for (int j2 = 0; j2 < 4; j2++) {
                unsigned boff = tswz((j2 << 4) + krl, 2 * ks + kcp);
                unsigned bh[4], bl[4];
                ldsm4(bh, sb + QK_WH + boff);
                ldsm4(bl, sb + QK_WL + boff);
                mmah(c[2*j2],   ax, bh[0], bh[1]);
                mmah(c[2*j2],   ax, bl[0], bl[1]);
                mmah(c[2*j2+1], ax, bh[2], bh[3]);
                mmah(c[2*j2+1], ax, bl[2], bl[3]);
            }
        }

        // ---- epilogue: single fp16 ----
        __half* Y = (z == 0) ? g_Q : (z == 1) ? g_K : g_V;
        const int row0 = m0 + (w << 4) + (l >> 2);
        const int col  = nt * 64 + 2 * (l & 3);
        #pragma unroll
        for (int j = 0; j < 8; j++) {
            size_t base0 = (size_t)row0 * HH + col + j * 8;
            size_t base1 = base0 + (size_t)8 * HH;
            *(unsigned*)(Y + base0) = packf2(c[j][0], c[j][1]);
            *(unsigned*)(Y + base1) = packf2(c[j][2], c[j][3]);
        }
        __syncthreads();     // MMA+epilogue done before next conversion overwrites WH/WL
    }
}

// ---------------------------------------------------------------------------
// fp16 flash attention, no-max softmax, single-precision fp16 operands.
// Double-buffered K and V; one commit/wait + two barriers per key tile.
// CTA: 128 queries x batch; 8 warps x 16 q-rows; 64-key tiles; d=256.
// ---------------------------------------------------------------------------
__global__ __launch_bounds__(256, 1) void attn_kernel(
    const int* __restrict__ lens,
    float* __restrict__ out)
{
    extern __shared__ char smc[];
    const unsigned sb = smem_u32(smc);
    const int tid = threadIdx.x;
    const int w   = tid >> 5;
    const int l   = tid & 31;
    const int b   = blockIdx.y;
    const int q0  = blockIdx.x * 128;
    const int len = lens[b];
    const int nkt = (len + 63) >> 6;

    const __half* gK = g_K + (size_t)b * LL * HH;
    const __half* gV = g_V + (size_t)b * LL * HH;

    // ---- prologue: group0 = {Q, K0, V0} ----
    {
        const __half* q = g_Q + (size_t)(b * LL + q0) * HH;
        #pragma unroll
        for (int it = 0; it < 16; it++) {
            int v = tid + it * 256;
            int r = v >> 5, c8 = v & 31;
            cp16(sb + SM_Q + tswz(r, c8), q + r * HH + c8 * 8);
        }
        #pragma unroll
        for (int it = 0; it < 8; it++) {
            int v = tid + it * 256;
            int r = v >> 5, c8 = v & 31;
            unsigned off = tswz(r, c8);
            cp16(sb + SM_K0 + off, gK + r * HH + c8 * 8);
            cp16(sb + SM_V0 + off, gV + r * HH + c8 * 8);
        }
        cp_commit();
    }

    float o[32][4];
    #pragma unroll
    for (int n = 0; n < 32; n++)
        #pragma unroll
        for (int e = 0; e < 4; e++) o[n][e] = 0.f;
    float rs0 = 0.f, rs1 = 0.f;

    // lane constants
    const int qrow = (w << 4) + (l & 15);
    const int qx   = l >> 4;
    const int qsw  = qrow & 7;
    const unsigned qb = SM_Q + (unsigned)qrow * 512;
    const int krl  = ((l & 16) >> 1) + (l & 7);
    const int kcp  = (l >> 3) & 1;
    const int vrl  = (((l >> 3) & 1) << 3) + (l & 7);
    const int vco  = l >> 4;

    // scale folded with log2(e): p = 2^(s * SC2)
    const float SC2 = 0.0625f * 1.4426950408889634f;

    for (int kt = 0; kt < nkt; kt++) {
        const int k0 = kt << 6;
        const int cur = kt & 1;
        const unsigned kbuf = cur ? SM_K1 : SM_K0;
        const unsigned vbuf = cur ? SM_V1 : SM_V0;

        // ---- prefetch K(t+1), V(t+1) into the other buffers ----
        if (kt + 1 < nkt) {
            const unsigned kn = cur ? SM_K0 : SM_K1;
            const unsigned vn = cur ? SM_V0 : SM_V1;
            const __half* kh = gK + (size_t)(k0 + 64) * HH;
            const __half* vh = gV + (size_t)(k0 + 64) * HH;
            #pragma unroll
            for (int it = 0; it < 8; it++) {
                int v = tid + it * 256;
                int r = v >> 5, c8 = v & 31;
                unsigned off = tswz(r, c8);
                cp16(sb + kn + off, kh + r * HH + c8 * 8);
                cp16(sb + vn + off, vh + r * HH + c8 * 8);
            }
        }
        cp_commit();
        cp_wait1();          // group(t) complete; group(t+1) may be in flight
        __syncthreads();

        // ---- S = Q K^T ----
        float s[8][4];
        #pragma unroll
        for (int j = 0; j < 8; j++)
            #pragma unroll
            for (int e = 0; e < 4; e++) s[j][e] = 0.f;

        #pragma unroll 8
        for (int ks = 0; ks < 16; ks++) {
            unsigned ah[4];
            int ach = 2 * ks + qx;
            ldsm4(ah, sb + qb + ((unsigned)((ach ^ qsw) << 4)));
            #pragma unroll
            for (int j2 = 0; j2 < 4; j2++) {
                unsigned bh[4];
                ldsm4(bh, sb + kbuf + tswz((j2 << 4) + krl, 2 * ks + kcp));
                mmah(s[2*j2],   ah, bh[0], bh[1]);
                mmah(s[2*j2+1], ah, bh[2], bh[3]);
            }
        }

        // ---- softmax (registers; P single fp16) ----
        unsigned aph[4][4];
        if (k0 + 64 <= len) {
            #pragma unroll
            for (int kk = 0; kk < 4; kk++) {
                #pragma unroll
                for (int h = 0; h < 2; h++) {
                    int j = 2 * kk + h;
                    float p0 = ex2(s[j][0] * SC2);
                    float p1 = ex2(s[j][1] * SC2);
                    float p2 = ex2(s[j][2] * SC2);
                    float p3 = ex2(s[j][3] * SC2);
                    rs0 += p0 + p1;
                    rs1 += p2 + p3;
                    aph[kk][2*h+0] = packf2(p0, p1);
                    aph[kk][2*h+1] = packf2(p2, p3);
                }
            }
        } else {
            #pragma unroll
            for (int kk = 0; kk < 4; kk++) {
                #pragma unroll
                for (int h = 0; h < 2; h++) {
                    int j = 2 * kk + h;
                    int col = k0 + 8 * j + 2 * (l & 3);
                    float p0 = (col     < len) ? ex2(s[j][0] * SC2) : 0.f;
                    float p1 = (col + 1 < len) ? ex2(s[j][1] * SC2) : 0.f;
                    float p2 = (col     < len) ? ex2(s[j][2] * SC2) : 0.f;
                    float p3 = (col + 1 < len) ? ex2(s[j][3] * SC2) : 0.f;
                    rs0 += p0 + p1;
                    rs1 += p2 + p3;
                    aph[kk][2*h+0] = packf2(p0, p1);
                    aph[kk][2*h+1] = packf2(p2, p3);
                }
            }
        }

        // ---- O += P V ----
        #pragma unroll
        for (int kk = 0; kk < 4; kk++) {
            #pragma unroll
            for (int j2 = 0; j2 < 16; j2++) {
                unsigned vh[4];
                ldsm4t(vh, sb + vbuf + tswz((kk << 4) + vrl, 2 * j2 + vco));
                mmah(o[2*j2],   aph[kk], vh[0], vh[1]);
                mmah(o[2*j2+1], aph[kk], vh[2], vh[3]);
            }
        }
        __syncthreads();     // all warps done with buf(cur) before it is refilled
    }

    // ---- epilogue ----
    rs0 += __shfl_xor_sync(0xffffffffu, rs0, 1);
    rs0 += __shfl_xor_sync(0xffffffffu, rs0, 2);
    rs1 += __shfl_xor_sync(0xffffffffu, rs1, 1);
    rs1 += __shfl_xor_sync(0xffffffffu, rs1, 2);
    const float inv0 = 1.f / rs0;
    const float inv1 = 1.f / rs1;

    const int row0 = q0 + (w << 4) + (l >> 2);
    const int row1 = row0 + 8;
    const int colb = 2 * (l & 3);
    float* o0 = out + (size_t)(b * LL + row0) * HH + colb;
    float* o1 = out + (size_t)(b * LL + row1) * HH + colb;
    #pragma unroll
    for (int n = 0; n < 32; n++) {
        *(float2*)(o0 + 8 * n) = make_float2(o[n][0] * inv0, o[n][1] * inv0);
        *(float2*)(o1 + 8 * n) = make_float2(o[n][2] * inv1, o[n][3] * inv1);
    }
}

// ---------------------------------------------------------------------------
extern "C" void kernel_launch(void* const* d_in, const int* in_sizes, int n_in,
                              void* d_out, int out_size)
{
    const float* X    = (const float*)d_in[0];
    const float* Wq   = (const float*)d_in[1];
    const float* Wk   = (const float*)d_in[2];
    const float* Wv   = (const float*)d_in[3];
    const int*   lens = (const int*)d_in[4];
    float* out = (float*)d_out;

    cudaFuncSetAttribute(qkv_mma_kernel,
                         cudaFuncAttributeMaxDynamicSharedMemorySize, SMEM_TOTAL);
    qkv_mma_kernel<<<dim3(MTOT / 128), 256, SMEM_TOTAL>>>(X, Wq, Wk, Wv);

    cudaFuncSetAttribute(attn_kernel,
                         cudaFuncAttributeMaxDynamicSharedMemorySize, SMEM_TOTAL);
    attn_kernel<<<dim3(LL / 128, BB), 256, SMEM_TOTAL>>>(lens, out);
}

// round 12
// speedup vs baseline: 7.9830x; 1.0206x over previous
#include <cuda_runtime.h>
#include <cuda_bf16.h>
#include <cuda_fp16.h>
#include <math.h>

#define BB 8
#define LL 2048
#define HH 256
#define MTOT (BB*LL)

// Projected tensors: single fp16. Row-major [b*L][H].
__device__ __align__(16) __half g_Q[MTOT*HH];
__device__ __align__(16) __half g_K[MTOT*HH];
__device__ __align__(16) __half g_V[MTOT*HH];

// Split-K partials: unnormalized O and row sums l, per split.
__device__ __align__(16) float g_Op[2][MTOT*HH];
__device__ float g_lp[2][MTOT];

// ---------------- helpers ----------------
__device__ __forceinline__ unsigned smem_u32(const void* p) {
    unsigned a;
    asm("{ .reg .u64 t; cvta.to.shared.u64 t, %1; cvt.u32.u64 %0, t; }" : "=r"(a) : "l"(p));
    return a;
}
__device__ __forceinline__ unsigned packf2(float e0, float e1) {
    unsigned r;  // low half = e0, high half = e1
    asm("cvt.rn.f16x2.f32 %0, %1, %2;" : "=r"(r) : "f"(e1), "f"(e0));
    return r;
}
__device__ __forceinline__ float ex2(float x) {
    float r;
    asm("ex2.approx.f32 %0, %1;" : "=f"(r) : "f"(x));
    return r;
}
__device__ __forceinline__ void ldsm4(unsigned* r, unsigned addr) {
    asm volatile("ldmatrix.sync.aligned.m8n8.x4.shared.b16 {%0,%1,%2,%3}, [%4];"
                 : "=r"(r[0]), "=r"(r[1]), "=r"(r[2]), "=r"(r[3]) : "r"(addr));
}
__device__ __forceinline__ void ldsm4t(unsigned* r, unsigned addr) {
    asm volatile("ldmatrix.sync.aligned.m8n8.x4.trans.shared.b16 {%0,%1,%2,%3}, [%4];"
                 : "=r"(r[0]), "=r"(r[1]), "=r"(r[2]), "=r"(r[3]) : "r"(addr));
}
__device__ __forceinline__ void mmah(float* c, const unsigned* a, unsigned b0, unsigned b1) {
    asm volatile(
        "mma.sync.aligned.m16n8k16.row.col.f32.f16.f16.f32 "
        "{%0,%1,%2,%3},{%4,%5,%6,%7},{%8,%9},{%0,%1,%2,%3};"
        : "+f"(c[0]), "+f"(c[1]), "+f"(c[2]), "+f"(c[3])
        : "r"(a[0]), "r"(a[1]), "r"(a[2]), "r"(a[3]), "r"(b0), "r"(b1));
}
__device__ __forceinline__ void cp16(unsigned dst, const void* src) {
    asm volatile("cp.async.cg.shared.global [%0], [%1], 16;" :: "r"(dst), "l"(src) : "memory");
}
__device__ __forceinline__ void cp_commit() { asm volatile("cp.async.commit_group;" ::: "memory"); }
__device__ __forceinline__ void cp_wait0()  { asm volatile("cp.async.wait_group 0;"  ::: "memory"); }
__device__ __forceinline__ void cp_wait1()  { asm volatile("cp.async.wait_group 1;"  ::: "memory"); }

// smem tile layout: rows of 256 x 16-bit = 512B = 32 16B-chunks, XOR swizzle.
__device__ __forceinline__ unsigned tswz(int r, int c8) {
    return (unsigned)(r * 512 + ((c8 ^ (r & 7)) << 4));
}

// attention smem layout: Q 64KB; K double-buffer 2x32KB; V double-buffer 2x32KB
#define SM_Q   0
#define SM_K0  65536
#define SM_K1  98304
#define SM_V0  131072
#define SM_V1  163840
#define SMEM_TOTAL 196608

// qkv smem layout: X fp16 64KB; W fp16 32KB; W fp32 staging 64KB
#define QK_X   0
#define QK_WH  65536
#define QK_WS  98304
#define QKV_SMEM 163840

// ---------------------------------------------------------------------------
// QKV projection on tensor cores, all single fp16 (1 pass).
// W tiles prefetched fp32 via cp.async into smem staging (latency hidden).
// ---------------------------------------------------------------------------
__global__ __launch_bounds__(256, 1) void qkv_mma_kernel(
    const float* __restrict__ X,
    const float* __restrict__ Wq,
    const float* __restrict__ Wk,
    const float* __restrict__ Wv)
{
    extern __shared__ char smc[];
    const unsigned sb = smem_u32(smc);
    const int tid = threadIdx.x;
    const int w   = tid >> 5;
    const int l   = tid & 31;
    const int m0  = blockIdx.x * 128;

    const float* Ws[3] = { Wq, Wk, Wv };

    // ---- issue cp.async for W tile 0 fp32 into staging ----
    #pragma unroll
    for (int it = 0; it < 16; it++) {
        int v = tid + it * 256;
        int r = v >> 6, c16 = v & 63;                 // 64 rows x 64 16B-chunks
        cp16(sb + QK_WS + r * 1024 + c16 * 16, Wq + (size_t)r * HH + c16 * 4);
    }
    cp_commit();

    // ---- X tile -> single fp16, swizzled (overlaps the W cp.async) ----
    #pragma unroll
    for (int it = 0; it < 16; it++) {
        int v = tid + it * 256;
        int r = v >> 5, c8 = v & 31;
        const float* src = X + (size_t)(m0 + r) * HH + c8 * 8;
        float4 a = *(const float4*)src;
        float4 c = *(const float4*)(src + 4);
        *(uint4*)(smc + QK_X + tswz(r, c8)) =
            make_uint4(packf2(a.x, a.y), packf2(a.z, a.w),
                       packf2(c.x, c.y), packf2(c.z, c.w));
    }

    const int qrow = (w << 4) + (l & 15);
    const int qx   = l >> 4;
    const int qsw  = qrow & 7;
    const unsigned xb = QK_X + (unsigned)qrow * 512;
    const int krl  = ((l & 16) >> 1) + (l & 7);
    const int kcp  = (l >> 3) & 1;

    #pragma unroll 1
    for (int t = 0; t < 12; t++) {
        const int z  = t >> 2;
        const int nt = t & 3;

        cp_wait0();
        __syncthreads();     // W(t) staging ready; previous MMA done with WH

        // ---- convert staging fp32 -> WH fp16 (swizzled) ----
        #pragma unroll
        for (int it = 0; it < 8; it++) {
            int v = tid + it * 256;
            int r = v >> 5, c8 = v & 31;
            const float* src = (const float*)(smc + QK_WS + r * 1024 + c8 * 32);
            float4 a = *(const float4*)src;
            float4 c = *(const float4*)(src + 4);
            *(uint4*)(smc + QK_WH + tswz(r, c8)) =
                make_uint4(packf2(a.x, a.y), packf2(a.z, a.w),
                           packf2(c.x, c.y), packf2(c.z, c.w));
        }
        __syncthreads();     // WH ready; staging free

        // ---- prefetch W(t+1) fp32 into staging ----
        if (t + 1 < 12) {
            const float* Wn = Ws[(t + 1) >> 2] + (size_t)(((t + 1) & 3) * 64) * HH;
            #pragma unroll
            for (int it = 0; it < 16; it++) {
                int v = tid + it * 256;
                int r = v >> 6, c16 = v & 63;
                cp16(sb + QK_WS + r * 1024 + c16 * 16, Wn + (size_t)r * HH + c16 * 4);
            }
        }
        cp_commit();

        // ---- MMA: Y = X * W^T ----
        float c[8][4];
        #pragma unroll
        for (int j = 0; j < 8; j++)
            #pragma unroll
            for (int e = 0; e < 4; e++) c[j][e] = 0.f;

        #pragma unroll 8
        for (int ks = 0; ks < 16; ks++) {
            unsigned ax[4];
            int ach = 2 * ks + qx;
            ldsm4(ax, sb + xb + ((unsigned)((ach ^ qsw) << 4)));
            #pragma unroll
            for (int j2 = 0; j2 < 4; j2++) {
                unsigned bh[4];
                ldsm4(bh, sb + QK_WH + tswz((j2 << 4) + krl, 2 * ks + kcp));
                mmah(c[2*j2],   ax, bh[0], bh[1]);
                mmah(c[2*j2+1], ax, bh[2], bh[3]);
            }
        }

        // ---- epilogue: single fp16 ----
        __half* Y = (z == 0) ? g_Q : (z == 1) ? g_K : g_V;
        const int row0 = m0 + (w << 4) + (l >> 2);
        const int col  = nt * 64 + 2 * (l & 3);
        #pragma unroll
        for (int j = 0; j < 8; j++) {
            size_t base0 = (size_t)row0 * HH + col + j * 8;
            size_t base1 = base0 + (size_t)8 * HH;
            *(unsigned*)(Y + base0) = packf2(c[j][0], c[j][1]);
            *(unsigned*)(Y + base1) = packf2(c[j][2], c[j][3]);
        }
        __syncthreads();     // MMA+epilogue done before next conversion overwrites WH
    }
}

// ---------------------------------------------------------------------------
// fp16 flash attention, no-max softmax, split-K=2.
// Each CTA covers half the key tiles of (q-tile, batch); writes unnormalized
// partial O and row-sum l to scratch. Partials merge by pure addition.
// ---------------------------------------------------------------------------
__global__ __launch_bounds__(256, 1) void attn_kernel(
    const int* __restrict__ lens)
{
    extern __shared__ char smc[];
    const unsigned sb = smem_u32(smc);
    const int tid = threadIdx.x;
    const int w   = tid >> 5;
    const int l   = tid & 31;
    const int b   = blockIdx.y;
    const int q0  = blockIdx.x * 128;
    const int sp  = blockIdx.z;
    const int len = lens[b];
    const int nkt = (len + 63) >> 6;
    const int chunk = (nkt + 1) >> 1;
    const int t0 = sp * chunk;
    const int t1 = (t0 + chunk < nkt) ? (t0 + chunk) : nkt;

    const __half* gK = g_K + (size_t)b * LL * HH;
    const __half* gV = g_V + (size_t)b * LL * HH;

    // ---- prologue: group0 = {Q, K(t0), V(t0)} ----
    if (t0 < t1) {
        const __half* q = g_Q + (size_t)(b * LL + q0) * HH;
        #pragma unroll
        for (int it = 0; it < 16; it++) {
            int v = tid + it * 256;
            int r = v >> 5, c8 = v & 31;
            cp16(sb + SM_Q + tswz(r, c8), q + r * HH + c8 * 8);
        }
        const __half* k0p = gK + (size_t)(t0 << 6) * HH;
        const __half* v0p = gV + (size_t)(t0 << 6) * HH;
        #pragma unroll
        for (int it = 0; it < 8; it++) {
            int v = tid + it * 256;
            int r = v >> 5, c8 = v & 31;
            unsigned off = tswz(r, c8);
            cp16(sb + SM_K0 + off, k0p + r * HH + c8 * 8);
            cp16(sb + SM_V0 + off, v0p + r * HH + c8 * 8);
        }
        cp_commit();
    }

    float o[32][4];
    #pragma unroll
    for (int n = 0; n < 32; n++)
        #pragma unroll
        for (int e = 0; e < 4; e++) o[n][e] = 0.f;
    float rs0 = 0.f, rs1 = 0.f;

    // lane constants
    const int qrow = (w << 4) + (l & 15);
    const int qx   = l >> 4;
    const int qsw  = qrow & 7;
    const unsigned qb = SM_Q + (unsigned)qrow * 512;
    const int krl  = ((l & 16) >> 1) + (l & 7);
    const int kcp  = (l >> 3) & 1;
    const int vrl  = (((l >> 3) & 1) << 3) + (l & 7);
    const int vco  = l >> 4;

    // scale folded with log2(e): p = 2^(s * SC2)
    const float SC2 = 0.0625f * 1.4426950408889634f;

    for (int kt = t0; kt < t1; kt++) {
        const int k0 = kt << 6;
        const int cur = (kt - t0) & 1;
        const unsigned kbuf = cur ? SM_K1 : SM_K0;
        const unsigned vbuf = cur ? SM_V1 : SM_V0;

        // ---- prefetch K(t+1), V(t+1) into the other buffers ----
        if (kt + 1 < t1) {
            const unsigned kn = cur ? SM_K0 : SM_K1;
            const unsigned vn = cur ? SM_V0 : SM_V1;
            const __half* kh = gK + (size_t)(k0 + 64) * HH;
            const __half* vh = gV + (size_t)(k0 + 64) * HH;
            #pragma unroll
            for (int it = 0; it < 8; it++) {
                int v = tid + it * 256;
                int r = v >> 5, c8 = v & 31;
                unsigned off = tswz(r, c8);
                cp16(sb + kn + off, kh + r * HH + c8 * 8);
                cp16(sb + vn + off, vh + r * HH + c8 * 8);
            }
        }
        cp_commit();
        cp_wait1();          // group(t) complete; group(t+1) may be in flight
        __syncthreads();

        // ---- S = Q K^T ----
        float s[8][4];
        #pragma unroll
        for (int j = 0; j < 8; j++)
            #pragma unroll
            for (int e = 0; e < 4; e++) s[j][e] = 0.f;

        #pragma unroll 8
        for (int ks = 0; ks < 16; ks++) {
            unsigned ah[4];
            int ach = 2 * ks + qx;
            ldsm4(ah, sb + qb + ((unsigned)((ach ^ qsw) << 4)));
            #pragma unroll
            for (int j2 = 0; j2 < 4; j2++) {
                unsigned bh[4];
                ldsm4(bh, sb + kbuf + tswz((j2 << 4) + krl, 2 * ks + kcp));
                mmah(s[2*j2],   ah, bh[0], bh[1]);
                mmah(s[2*j2+1], ah, bh[2], bh[3]);
            }
        }

        // ---- softmax (registers; P single fp16) ----
        unsigned aph[4][4];
        if (k0 + 64 <= len) {
            #pragma unroll
            for (int kk = 0; kk < 4; kk++) {
                #pragma unroll
                for (int h = 0; h < 2; h++) {
                    int j = 2 * kk + h;
                    float p0 = ex2(s[j][0] * SC2);
                    float p1 = ex2(s[j][1] * SC2);
                    float p2 = ex2(s[j][2] * SC2);
                    float p3 = ex2(s[j][3] * SC2);
                    rs0 += p0 + p1;
                    rs1 += p2 + p3;
                    aph[kk][2*h+0] = packf2(p0, p1);
                    aph[kk][2*h+1] = packf2(p2, p3);
                }
            }
        } else {
            #pragma unroll
            for (int kk = 0; kk < 4; kk++) {
                #pragma unroll
                for (int h = 0; h < 2; h++) {
                    int j = 2 * kk + h;
                    int col = k0 + 8 * j + 2 * (l & 3);
                    float p0 = (col     < len) ? ex2(s[j][0] * SC2) : 0.f;
                    float p1 = (col + 1 < len) ? ex2(s[j][1] * SC2) : 0.f;
                    float p2 = (col     < len) ? ex2(s[j][2] * SC2) : 0.f;
                    float p3 = (col + 1 < len) ? ex2(s[j][3] * SC2) : 0.f;
                    rs0 += p0 + p1;
                    rs1 += p2 + p3;
                    aph[kk][2*h+0] = packf2(p0, p1);
                    aph[kk][2*h+1] = packf2(p2, p3);
                }
            }
        }

        // ---- O += P V ----
        #pragma unroll
        for (int kk = 0; kk < 4; kk++) {
            #pragma unroll
            for (int j2 = 0; j2 < 16; j2++) {
                unsigned vh[4];
                ldsm4t(vh, sb + vbuf + tswz((kk << 4) + vrl, 2 * j2 + vco));
                mmah(o[2*j2],   aph[kk], vh[0], vh[1]);
                mmah(o[2*j2+1], aph[kk], vh[2], vh[3]);
            }
        }
        __syncthreads();     // all warps done with buf(cur) before it is refilled
    }

    // ---- epilogue: write unnormalized partials ----
    rs0 += __shfl_xor_sync(0xffffffffu, rs0, 1);
    rs0 += __shfl_xor_sync(0xffffffffu, rs0, 2);
    rs1 += __shfl_xor_sync(0xffffffffu, rs1, 1);
    rs1 += __shfl_xor_sync(0xffffffffu, rs1, 2);

    const int row0 = q0 + (w << 4) + (l >> 2);
    const int row1 = row0 + 8;
    const int colb = 2 * (l & 3);
    float* o0 = g_Op[sp] + (size_t)(b * LL + row0) * HH + colb;
    float* o1 = g_Op[sp] + (size_t)(b * LL + row1) * HH + colb;
    #pragma unroll
    for (int n = 0; n < 32; n++) {
        *(float2*)(o0 + 8 * n) = make_float2(o[n][0], o[n][1]);
        *(float2*)(o1 + 8 * n) = make_float2(o[n][2], o[n][3]);
    }
    if ((l & 3) == 0) {
        g_lp[sp][b * LL + row0] = rs0;
        g_lp[sp][b * LL + row1] = rs1;
    }
}

// ---------------------------------------------------------------------------
// Merge: out = (O0 + O1) / (l0 + l1), float4 per thread iteration.
// ---------------------------------------------------------------------------
__global__ __launch_bounds__(256) void merge_kernel(float* __restrict__ out)
{
    const int idx = blockIdx.x * 256 + threadIdx.x;   // float4 index
    const int row = idx >> 6;                          // HH/4 = 64 float4 per row
    const float inv = 1.f / (g_lp[0][row] + g_lp[1][row]);
    const float4 a = *((const float4*)g_Op[0] + idx);
    const float4 c = *((const float4*)g_Op[1] + idx);
    float4 r;
    r.x = (a.x + c.x) * inv;
    r.y = (a.y + c.y) * inv;
    r.z = (a.z + c.z) * inv;
    r.w = (a.w + c.w) * inv;
    *((float4*)out + idx) = r;
}

// ---------------------------------------------------------------------------
extern "C" void kernel_launch(void* const* d_in, const int* in_sizes, int n_in,
                              void* d_out, int out_size)
{
    const float* X    = (const float*)d_in[0];
    const float* Wq   = (const float*)d_in[1];
    const float* Wk   = (const float*)d_in[2];
    const float* Wv   = (const float*)d_in[3];
    const int*   lens = (const int*)d_in[4];
    float* out = (float*)d_out;

    cudaFuncSetAttribute(qkv_mma_kernel,
                         cudaFuncAttributeMaxDynamicSharedMemorySize, QKV_SMEM);
    qkv_mma_kernel<<<dim3(MTOT / 128), 256, QKV_SMEM>>>(X, Wq, Wk, Wv);

    cudaFuncSetAttribute(attn_kernel,
                         cudaFuncAttributeMaxDynamicSharedMemorySize, SMEM_TOTAL);
    attn_kernel<<<dim3(LL / 128, BB, 2), 256, SMEM_TOTAL>>>(lens);

    merge_kernel<<<dim3(MTOT * HH / 4 / 256), 256>>>(out);
}